// round 13
// baseline (speedup 1.0000x reference)
#include <cuda_runtime.h>
#include <cstdint>

// GATv2 GNN, one CTA per batch element, 1024 threads (32 warps, occ 50%).
// Round 13: 1024-thread retile of r12. GEMM split L/R across warp halves
// (fits 64-reg budget), compute_e ICNT=16, aggregate FW=8. All validated
// layouts preserved (RS=132, EJS=68, j=t&63 mappings).

#define RS 132
#define NT 1024
#define EJS 68
#define NEGV -1000000000.0f

#define OFF_X   0
#define OFF_XL  (64*RS)
#define OFF_XR  (2*64*RS)
#define OFF_E   (3*64*RS)
#define E_FLOATS (4*64*EJS)
#define OFF_MS  (OFF_E + E_FLOATS)
#define OFF_SS  (OFF_MS + 1024)
#define OFF_IMP (OFF_SS + 1024)
#define OFF_DL  (OFF_IMP + 64)
#define OFF_DR  (OFF_DL + 256)
#define SMEM_FLOATS (OFF_DR + 256)
#define SMEM_BYTES  (SMEM_FLOATS * 4)   // 181504 B

// Fragment-packed tf32 weights (layout documented in pack kernel).
__device__ __align__(16) unsigned WPACKU[163840];
#define U_WL1 0
#define U_WR1 32768
#define U_WL2 65536
#define U_WR2 98304
#define U_WL3 131072
#define U_WR3 147456

__device__ __forceinline__ unsigned cvt_tf32(float f) {
    unsigned u; asm("cvt.rna.tf32.f32 %0, %1;" : "=r"(u) : "f"(f)); return u;
}

// ---- packed f32x2 helpers ----
__device__ __forceinline__ uint64_t pk2(float lo, float hi) {
    uint64_t d; asm("mov.b64 %0, {%1, %2};" : "=l"(d) : "f"(lo), "f"(hi)); return d;
}
__device__ __forceinline__ float2 upk2(uint64_t v) {
    float lo, hi; asm("mov.b64 {%0, %1}, %2;" : "=f"(lo), "=f"(hi) : "l"(v));
    return make_float2(lo, hi);
}
__device__ __forceinline__ uint64_t fadd2(uint64_t a, uint64_t b) {
    uint64_t d; asm("add.rn.f32x2 %0, %1, %2;" : "=l"(d) : "l"(a), "l"(b)); return d;
}
__device__ __forceinline__ void ffma2(uint64_t& d, uint64_t a, uint64_t b, uint64_t c) {
    asm("fma.rn.f32x2 %0, %1, %2, %3;" : "=l"(d) : "l"(a), "l"(b), "l"(c));
}

__device__ __forceinline__ void mma_tf32(float* d, unsigned a0, unsigned a1,
                                         unsigned a2, unsigned a3,
                                         unsigned b0, unsigned b1) {
    asm volatile(
        "mma.sync.aligned.m16n8k8.row.col.f32.tf32.tf32.f32 "
        "{%0,%1,%2,%3}, {%4,%5,%6,%7}, {%8,%9}, {%0,%1,%2,%3};"
        : "+f"(d[0]), "+f"(d[1]), "+f"(d[2]), "+f"(d[3])
        : "r"(a0), "r"(a1), "r"(a2), "r"(a3), "r"(b0), "r"(b1));
}

// ---------------------------------------------------------------------------
// Weight pack kernel (identical layout to round 8).
// ---------------------------------------------------------------------------
__global__ void pack_weights_tf32(
    const float* __restrict__ Wl1, const float* __restrict__ Wr1,
    const float* __restrict__ Wl2, const float* __restrict__ Wr2,
    const float* __restrict__ Wl3, const float* __restrict__ Wr3)
{
    int idx = blockIdx.x * blockDim.x + threadIdx.x;
    if (idx >= 163840) return;
    const float* src; int fout, ngc, e;
    if      (idx < 32768)  { src = Wl1; fout = 128; ngc = 4; e = idx; }
    else if (idx < 65536)  { src = Wr1; fout = 128; ngc = 4; e = idx - 32768; }
    else if (idx < 98304)  { src = Wl2; fout = 128; ngc = 4; e = idx - 65536; }
    else if (idx < 131072) { src = Wr2; fout = 128; ngc = 4; e = idx - 98304; }
    else if (idx < 147456) { src = Wl3; fout = 64;  ngc = 2; e = idx - 131072; }
    else                   { src = Wr3; fout = 64;  ngc = 2; e = idx - 147456; }

    int big = e >> 7;
    int r = e & 127;
    int lane = r >> 2, nt = r & 3;
    int gid = lane >> 2, tig = lane & 3;
    int ng = big % ngc;
    int t2 = big / ngc;
    int breg = t2 & 1;
    int part = (t2 >> 1) & 1;
    int kb = t2 >> 2;
    int row = kb * 8 + tig + breg * 4;
    int col = ng * 32 + nt * 8 + gid;
    float v = src[row * fout + col];
    unsigned hi = cvt_tf32(v);
    unsigned outv = hi;
    if (part) outv = cvt_tf32(v - __uint_as_float(hi));
    WPACKU[idx] = outv;
}

// ---------------------------------------------------------------------------
// Single-output GEMM: warps [0, 4*NG) compute XL (+dl partials),
// warps [4*NG, 8*NG) compute XR (+dr). m16n8k8 tf32, 3-term split.
// FOUT=128: full dl/dr per (row, head=ng). FOUT=64: 2 partials/row.
// ---------------------------------------------------------------------------
template <int FOUT>
__device__ void dual_matmul_mma(const unsigned* __restrict__ baseL,
                                const unsigned* __restrict__ baseR,
                                const float* xbuf, float* xlbuf, float* xrbuf,
                                const float* __restrict__ att,
                                float* DLp, float* DRp)
{
    constexpr int NG = FOUT / 32;          // 4 or 2
    constexpr int NWP = 4 * NG;            // warps per matrix: 16 or 8
    const int w = threadIdx.x >> 5;
    if (w >= 2 * NWP) return;
    const int which = (w >= NWP) ? 1 : 0;  // 0 = L, 1 = R
    const int wl = which ? (w - NWP) : w;
    const int lane = threadIdx.x & 31;
    const int gid = lane >> 2, tig = lane & 3;
    const int mt = wl / NG, ng = wl % NG;
    const int m0 = mt * 16;
    const int n0 = ng * 32;

    const unsigned* base = which ? baseR : baseL;
    float* outbuf = which ? xrbuf : xlbuf;
    float* dout   = which ? DRp : DLp;

    float d[4][4];
#pragma unroll
    for (int nt = 0; nt < 4; nt++)
#pragma unroll
        for (int q = 0; q < 4; q++) d[nt][q] = 0.f;

    constexpr int KB_STRIDE = 4 * NG * 128;
    constexpr int OFS = NG * 128;
    const unsigned* p = base + ng * 128 + lane * 4;
    const float* xrow = xbuf + (m0 + gid) * RS + tig;

#pragma unroll 2
    for (int kb = 0; kb < 16; kb++) {
        float a0f = xrow[kb * 8];
        float a1f = xrow[kb * 8 + 8 * RS];
        float a2f = xrow[kb * 8 + 4];
        float a3f = xrow[kb * 8 + 8 * RS + 4];
        unsigned ah0 = cvt_tf32(a0f), ah1 = cvt_tf32(a1f);
        unsigned ah2 = cvt_tf32(a2f), ah3 = cvt_tf32(a3f);
        unsigned al0 = cvt_tf32(a0f - __uint_as_float(ah0));
        unsigned al1 = cvt_tf32(a1f - __uint_as_float(ah1));
        unsigned al2 = cvt_tf32(a2f - __uint_as_float(ah2));
        unsigned al3 = cvt_tf32(a3f - __uint_as_float(ah3));

        const unsigned* q = p + kb * KB_STRIDE;
        uint4 HB0 = *(const uint4*)(q);
        uint4 HB1 = *(const uint4*)(q + OFS);
        uint4 LB0 = *(const uint4*)(q + 2 * OFS);
        uint4 LB1 = *(const uint4*)(q + 3 * OFS);
        const unsigned* h0 = (const unsigned*)&HB0;
        const unsigned* h1 = (const unsigned*)&HB1;
        const unsigned* l0 = (const unsigned*)&LB0;
        const unsigned* l1 = (const unsigned*)&LB1;

#pragma unroll
        for (int nt = 0; nt < 4; nt++) {
            mma_tf32(d[nt], ah0, ah1, ah2, ah3, h0[nt], h1[nt]);   // Ah*Bh
            mma_tf32(d[nt], al0, al1, al2, al3, h0[nt], h1[nt]);   // Al*Bh
            mma_tf32(d[nt], ah0, ah1, ah2, ah3, l0[nt], l1[nt]);   // Ah*Bl
        }
    }

    const int rowa = m0 + gid, rowb = m0 + gid + 8;
#pragma unroll
    for (int nt = 0; nt < 4; nt++) {
        const int col = n0 + nt * 8 + 2 * tig;
        *(float2*)(outbuf + rowa * RS + col) = make_float2(d[nt][0], d[nt][1]);
        *(float2*)(outbuf + rowb * RS + col) = make_float2(d[nt][2], d[nt][3]);
    }

    // fused dl/dr partial over this warp's 32 columns.
    float pa = 0.f, pb = 0.f;
#pragma unroll
    for (int nt = 0; nt < 4; nt++) {
        float2 av = *(const float2*)(att + n0 + nt * 8 + 2 * tig);
        pa = fmaf(d[nt][0], av.x, fmaf(d[nt][1], av.y, pa));
        pb = fmaf(d[nt][2], av.x, fmaf(d[nt][3], av.y, pb));
    }
#pragma unroll
    for (int o = 1; o < 4; o <<= 1) {
        pa += __shfl_xor_sync(0xffffffffu, pa, o);
        pb += __shfl_xor_sync(0xffffffffu, pb, o);
    }
    if (tig == 0) {
        dout[rowa * NG + ng] = pa;
        dout[rowb * NG + ng] = pb;
    }
}

// ---------------------------------------------------------------------------
// compute_e + fused softmax (1024 threads). Writes alpha into E[h][j][i].
// Thread: j=t&63, rest=t>>6 (16) -> (h, ic); ICNT = 4*HH (16 or 4).
// DL3PART: HH==1 reads dl_i = DL[2i]+DL[2i+1].
// ---------------------------------------------------------------------------
template <int HH, int CC, bool DL3PART>
__device__ void compute_e_softmax(const float* xlbuf, const float* xrbuf,
                                  const float* __restrict__ att,
                                  const float* DLp, const float* DRp,
                                  float* ebuf, const int* imp, float* MS, float* SS)
{
    const int t = threadIdx.x;
    const int j = t & 63;
    const int rest = t >> 6;            // 0..15
    const int h = rest % HH;
    const int ic = rest / HH;
    constexpr int ICNT = 4 * HH;        // 16 (L1/2) or 4 (L3)
    const int i0 = ic * ICNT;
    constexpr uint64_t ABSM = 0x7FFFFFFF7FFFFFFFULL;

    float eacc[ICNT];
#pragma unroll
    for (int ii = 0; ii < ICNT; ii++) eacc[ii] = 0.f;

#pragma unroll
    for (int ch = 0; ch < CC / 16; ch++) {
        uint64_t xr2[8], av2[8];
        {
            const ulonglong2* xp = (const ulonglong2*)(xrbuf + j * RS + h * CC + ch * 16);
            const ulonglong2* ap = (const ulonglong2*)(att + h * CC + ch * 16);
#pragma unroll
            for (int q = 0; q < 4; q++) {
                ulonglong2 xv = xp[q]; xr2[2*q] = xv.x; xr2[2*q+1] = xv.y;
                ulonglong2 av = ap[q]; av2[2*q] = av.x; av2[2*q+1] = av.y;
            }
        }
#pragma unroll
        for (int ii = 0; ii < ICNT; ii++) {
            const ulonglong2* xl2 = (const ulonglong2*)(xlbuf + (i0 + ii) * RS + h * CC + ch * 16);
            uint64_t s2 = 0ull;
#pragma unroll
            for (int q = 0; q < 4; q++) {
                ulonglong2 xv = xl2[q];
                uint64_t z0 = fadd2(xv.x, xr2[2*q])     & ABSM;
                uint64_t z1 = fadd2(xv.y, xr2[2*q + 1]) & ABSM;
                ffma2(s2, z0, av2[2*q], s2);
                ffma2(s2, z1, av2[2*q + 1], s2);
            }
            float2 s = upk2(s2);
            eacc[ii] += s.x + s.y;
        }
    }

    const int impj = imp[j];
    float drv;
    if constexpr (DL3PART) drv = DRp[j * 2] + DRp[j * 2 + 1];
    else                   drv = DRp[j * HH + h];
#pragma unroll
    for (int ii = 0; ii < ICNT; ii++) {
        const int i = i0 + ii;
        float dlv;
        if constexpr (DL3PART) dlv = DLp[i * 2] + DLp[i * 2 + 1];
        else                   dlv = DLp[i * HH + h];
        float e = fmaf(0.4f, eacc[ii], 0.6f * (dlv + drv));
        bool ok = (i == j) || (impj && imp[i]);
        eacc[ii] = ok ? e : NEGV;
    }

    float m_t = eacc[0];
#pragma unroll
    for (int ii = 1; ii < ICNT; ii++) m_t = fmaxf(m_t, eacc[ii]);
    float s_t = 0.f;
#pragma unroll
    for (int ii = 0; ii < ICNT; ii++) {
        float ex = __expf(eacc[ii] - m_t);
        eacc[ii] = ex;
        s_t += ex;
    }
    MS[t] = m_t; SS[t] = s_t;
    __syncthreads();

    constexpr int NG2 = 16 / HH;        // 4 or 16
    const int base = t & (64 * HH - 1);
    float M = -3.4e38f;
#pragma unroll
    for (int g = 0; g < NG2; g++) M = fmaxf(M, MS[base + g * 64 * HH]);
    float S = 0.f;
#pragma unroll
    for (int g = 0; g < NG2; g++)
        S = fmaf(SS[base + g * 64 * HH], __expf(MS[base + g * 64 * HH] - M), S);
    const float kfac = __expf(m_t - M) / S;

    float* dst = ebuf + (h * 64 + j) * EJS + i0;
#pragma unroll
    for (int ii = 0; ii < ICNT; ii += 4) {
        float4 o;
        o.x = eacc[ii] * kfac;     o.y = eacc[ii + 1] * kfac;
        o.z = eacc[ii + 2] * kfac; o.w = eacc[ii + 3] * kfac;
        *(float4*)(dst + ii) = o;
    }
}

// ---------------------------------------------------------------------------
// out[j][f] = sum_i alpha[h][j][i] * xl[i][f] + bias[f]
// 1024 threads: j = t&63, fs = t>>6 (16 slices of FOUT/16 floats).
// ---------------------------------------------------------------------------
template <int CC, int FOUT>
__device__ void aggregate(const float* xlbuf, const float* ebuf,
                          const float* __restrict__ bias, float* dst, int ds)
{
    const int t = threadIdx.x;
    const int j = t & 63;
    const int fs = t >> 6;
    constexpr int FW = FOUT / 16;       // 8 or 4
    const int f0 = fs * FW;
    const int h = f0 / CC;
    const float* arow = ebuf + (h * 64 + j) * EJS;

    uint64_t acc[FW / 2];
#pragma unroll
    for (int c = 0; c < FW / 2; c++) acc[c] = 0ull;

#pragma unroll 2
    for (int ib = 0; ib < 64; ib += 4) {
        float4 a4 = *(const float4*)(arow + ib);
#pragma unroll
        for (int u = 0; u < 4; u++) {
            float as = (u == 0) ? a4.x : (u == 1) ? a4.y : (u == 2) ? a4.z : a4.w;
            uint64_t ap = pk2(as, as);
            const float* xlr = xlbuf + (ib + u) * RS + f0;
            if constexpr (FW == 8) {
                ulonglong2 xv = *(const ulonglong2*)(xlr);
                ulonglong2 xw = *(const ulonglong2*)(xlr + 4);
                ffma2(acc[0], ap, xv.x, acc[0]);
                ffma2(acc[1], ap, xv.y, acc[1]);
                ffma2(acc[2], ap, xw.x, acc[2]);
                ffma2(acc[3], ap, xw.y, acc[3]);
            } else {
                ulonglong2 xv = *(const ulonglong2*)(xlr);
                ffma2(acc[0], ap, xv.x, acc[0]);
                ffma2(acc[1], ap, xv.y, acc[1]);
            }
        }
    }
#pragma unroll
    for (int c = 0; c < FW / 2; c += 2) {
        float2 lo = upk2(acc[c]);
        float2 hi = upk2(acc[c + 1]);
        float4 bv = *(const float4*)(bias + f0 + c * 2);
        float4 o;
        o.x = lo.x + bv.x; o.y = lo.y + bv.y;
        o.z = hi.x + bv.z; o.w = hi.y + bv.w;
        *(float4*)(dst + j * ds + f0 + c * 2) = o;
    }
}

// layernorm over 128 features + relu, in place. Warp per row, 2 rows per warp.
__device__ void ln_relu(float* xbuf, const float* __restrict__ g, const float* __restrict__ bb)
{
    const int w = threadIdx.x >> 5;
    const int lane = threadIdx.x & 31;
    for (int r = w; r < 64; r += 32) {
        float4 v = *(const float4*)(xbuf + r * RS + lane * 4);
        float sum = v.x + v.y + v.z + v.w;
        float sq  = v.x*v.x + v.y*v.y + v.z*v.z + v.w*v.w;
#pragma unroll
        for (int o = 16; o > 0; o >>= 1) {
            sum += __shfl_xor_sync(0xffffffffu, sum, o);
            sq  += __shfl_xor_sync(0xffffffffu, sq, o);
        }
        float mean = sum * (1.f / 128.f);
        float var  = sq * (1.f / 128.f) - mean * mean;
        float rstd = rsqrtf(var + 1e-5f);
        float4 gg = *(const float4*)(g + lane * 4);
        float4 bv = *(const float4*)(bb + lane * 4);
        float4 o;
        o.x = fmaxf((v.x - mean) * rstd * gg.x + bv.x, 0.f);
        o.y = fmaxf((v.y - mean) * rstd * gg.y + bv.y, 0.f);
        o.z = fmaxf((v.z - mean) * rstd * gg.z + bv.z, 0.f);
        o.w = fmaxf((v.w - mean) * rstd * gg.w + bv.w, 0.f);
        *(float4*)(xbuf + r * RS + lane * 4) = o;
    }
}

__global__ void __launch_bounds__(NT, 1)
GNN_61040075210810_kernel(
    const float* __restrict__ team_obs, const float* __restrict__ target_obs,
    const float* __restrict__ team_mask, const float* __restrict__ ltm,
    const float* __restrict__ W_emb, const float* __restrict__ b_emb,
    const float* __restrict__ att1, const float* __restrict__ b1,
    const float* __restrict__ att2, const float* __restrict__ b2,
    const float* __restrict__ att3, const float* __restrict__ b3,
    const float* __restrict__ ln1g, const float* __restrict__ ln1b,
    const float* __restrict__ ln2g, const float* __restrict__ ln2b,
    float* __restrict__ out)
{
    extern __shared__ float smf[];
    float* X  = smf + OFF_X;
    float* XL = smf + OFF_XL;
    float* XR = smf + OFF_XR;
    float* E  = smf + OFF_E;
    float* MS = smf + OFF_MS;
    float* SS = smf + OFF_SS;
    int*   IMP = (int*)(smf + OFF_IMP);
    float* DL = smf + OFF_DL;
    float* DR = smf + OFF_DR;

    const int b = blockIdx.x;
    const int t = threadIdx.x;

    // ---- feature assembly ----
    float* FIN = E;
    {
        int m = t >> 4, k = t & 15;
        float v;
        if (m < 16) {
            v = (k < 14) ? team_obs[(b * 16 + m) * 14 + k] : 0.f;
        } else {
            int tt = m - 16;
            if (k < 12)      v = target_obs[(b * 48 + tt) * 15 + k];
            else if (k < 14) v = 0.f;
            else             v = target_obs[(b * 48 + tt) * 15 + (k - 2)];
        }
        FIN[t] = v;
    }
    if (t < 64) {
        bool ok = (t < 16) ? (team_mask[b * 32 + t] != NEGV)
                           : (ltm[b * 49 + (t - 16)] != 0.0f);
        IMP[t] = ok ? 1 : 0;
    }
    __syncthreads();

    // ---- embedding: 2 rows per warp ----
    {
        const int w = t >> 5, lane = t & 31;
        const int row0 = w * 2;
        float acc[2][4];
#pragma unroll
        for (int r = 0; r < 2; r++)
#pragma unroll
            for (int c = 0; c < 4; c++) acc[r][c] = 0.f;
#pragma unroll
        for (int k = 0; k < 16; k++) {
            float xv[2];
#pragma unroll
            for (int r = 0; r < 2; r++) xv[r] = FIN[(row0 + r) * 16 + k];
            float4 wv = *(const float4*)(W_emb + k * 128 + lane * 4);
#pragma unroll
            for (int r = 0; r < 2; r++) {
                acc[r][0] = fmaf(xv[r], wv.x, acc[r][0]);
                acc[r][1] = fmaf(xv[r], wv.y, acc[r][1]);
                acc[r][2] = fmaf(xv[r], wv.z, acc[r][2]);
                acc[r][3] = fmaf(xv[r], wv.w, acc[r][3]);
            }
        }
        float4 be = *(const float4*)(b_emb + lane * 4);
#pragma unroll
        for (int r = 0; r < 2; r++) {
            float4 o;
            o.x = acc[r][0] + be.x; o.y = acc[r][1] + be.y;
            o.z = acc[r][2] + be.z; o.w = acc[r][3] + be.w;
            *(float4*)(X + (row0 + r) * RS + lane * 4) = o;
        }
    }
    __syncthreads();

    // ---- layer 1 ----
    dual_matmul_mma<128>(WPACKU + U_WL1, WPACKU + U_WR1, X, XL, XR, att1, DL, DR);
    __syncthreads();
    compute_e_softmax<4, 32, false>(XL, XR, att1, DL, DR, E, IMP, MS, SS);
    __syncthreads();
    aggregate<32, 128>(XL, E, b1, X, RS);
    __syncthreads();
    ln_relu(X, ln1g, ln1b);
    __syncthreads();

    // ---- layer 2 ----
    dual_matmul_mma<128>(WPACKU + U_WL2, WPACKU + U_WR2, X, XL, XR, att2, DL, DR);
    __syncthreads();
    compute_e_softmax<4, 32, false>(XL, XR, att2, DL, DR, E, IMP, MS, SS);
    __syncthreads();
    aggregate<32, 128>(XL, E, b2, X, RS);
    __syncthreads();
    ln_relu(X, ln2g, ln2b);
    __syncthreads();

    // ---- layer 3 (dl/dr fused into GEMM epilogue as 2 partials/row) ----
    dual_matmul_mma<64>(WPACKU + U_WL3, WPACKU + U_WR3, X, XL, XR, att3, DL, DR);
    __syncthreads();
    compute_e_softmax<1, 64, true>(XL, XR, att3, DL, DR, E, IMP, MS, SS);
    __syncthreads();
    aggregate<64, 64>(XL, E, b3, out + b * 64 * 64, 64);
}

extern "C" void kernel_launch(void* const* d_in, const int* in_sizes, int n_in,
                              void* d_out, int out_size)
{
    (void)in_sizes; (void)n_in; (void)out_size;
    pack_weights_tf32<<<640, 256>>>(
        (const float*)d_in[6],  (const float*)d_in[7],
        (const float*)d_in[10], (const float*)d_in[11],
        (const float*)d_in[14], (const float*)d_in[15]);

    cudaFuncSetAttribute(GNN_61040075210810_kernel,
                         cudaFuncAttributeMaxDynamicSharedMemorySize, SMEM_BYTES);
    GNN_61040075210810_kernel<<<128, NT, SMEM_BYTES>>>(
        (const float*)d_in[0],  (const float*)d_in[1],
        (const float*)d_in[2],  (const float*)d_in[3],
        (const float*)d_in[4],  (const float*)d_in[5],
        (const float*)d_in[8],  (const float*)d_in[9],
        (const float*)d_in[12], (const float*)d_in[13],
        (const float*)d_in[16], (const float*)d_in[17],
        (const float*)d_in[18], (const float*)d_in[19],
        (const float*)d_in[20], (const float*)d_in[21],
        (float*)d_out);
}

// round 14
// speedup vs baseline: 1.5413x; 1.5413x over previous
#include <cuda_runtime.h>
#include <cstdint>

// GATv2 GNN, one CTA per batch element, 512 threads.
// Round 14: r12 base + dependency-chain scheduling fixes only:
//   (1) GEMM MMA issue order term-major (dep reuse distance 1 -> 8)
//   (2) compute_e dual accumulators (ffma2 chain 8 -> 4)

#define RS 132
#define NT 512
#define EJS 68
#define NEGV -1000000000.0f

#define OFF_X   0
#define OFF_XL  (64*RS)
#define OFF_XR  (2*64*RS)
#define OFF_E   (3*64*RS)
#define E_FLOATS (4*64*EJS)
#define OFF_MS  (OFF_E + E_FLOATS)
#define OFF_SS  (OFF_MS + 512)
#define OFF_IMP (OFF_SS + 512)
#define OFF_DL  (OFF_IMP + 64)
#define OFF_DR  (OFF_DL + 256)
#define SMEM_FLOATS (OFF_DR + 256)
#define SMEM_BYTES  (SMEM_FLOATS * 4)   // 177408 B

// Fragment-packed tf32 weights (layout documented in pack kernel).
__device__ __align__(16) unsigned WPACKU[163840];
#define U_WL1 0
#define U_WR1 32768
#define U_WL2 65536
#define U_WR2 98304
#define U_WL3 131072
#define U_WR3 147456

__device__ __forceinline__ unsigned cvt_tf32(float f) {
    unsigned u; asm("cvt.rna.tf32.f32 %0, %1;" : "=r"(u) : "f"(f)); return u;
}

// ---- packed f32x2 helpers ----
__device__ __forceinline__ uint64_t pk2(float lo, float hi) {
    uint64_t d; asm("mov.b64 %0, {%1, %2};" : "=l"(d) : "f"(lo), "f"(hi)); return d;
}
__device__ __forceinline__ float2 upk2(uint64_t v) {
    float lo, hi; asm("mov.b64 {%0, %1}, %2;" : "=f"(lo), "=f"(hi) : "l"(v));
    return make_float2(lo, hi);
}
__device__ __forceinline__ uint64_t fadd2(uint64_t a, uint64_t b) {
    uint64_t d; asm("add.rn.f32x2 %0, %1, %2;" : "=l"(d) : "l"(a), "l"(b)); return d;
}
__device__ __forceinline__ void ffma2(uint64_t& d, uint64_t a, uint64_t b, uint64_t c) {
    asm("fma.rn.f32x2 %0, %1, %2, %3;" : "=l"(d) : "l"(a), "l"(b), "l"(c));
}

__device__ __forceinline__ void mma_tf32(float* d, unsigned a0, unsigned a1,
                                         unsigned a2, unsigned a3,
                                         unsigned b0, unsigned b1) {
    asm volatile(
        "mma.sync.aligned.m16n8k8.row.col.f32.tf32.tf32.f32 "
        "{%0,%1,%2,%3}, {%4,%5,%6,%7}, {%8,%9}, {%0,%1,%2,%3};"
        : "+f"(d[0]), "+f"(d[1]), "+f"(d[2]), "+f"(d[3])
        : "r"(a0), "r"(a1), "r"(a2), "r"(a3), "r"(b0), "r"(b1));
}

// ---------------------------------------------------------------------------
// Weight pack kernel (identical layout to round 8).
// ---------------------------------------------------------------------------
__global__ void pack_weights_tf32(
    const float* __restrict__ Wl1, const float* __restrict__ Wr1,
    const float* __restrict__ Wl2, const float* __restrict__ Wr2,
    const float* __restrict__ Wl3, const float* __restrict__ Wr3)
{
    int idx = blockIdx.x * blockDim.x + threadIdx.x;
    if (idx >= 163840) return;
    const float* src; int fout, ngc, e;
    if      (idx < 32768)  { src = Wl1; fout = 128; ngc = 4; e = idx; }
    else if (idx < 65536)  { src = Wr1; fout = 128; ngc = 4; e = idx - 32768; }
    else if (idx < 98304)  { src = Wl2; fout = 128; ngc = 4; e = idx - 65536; }
    else if (idx < 131072) { src = Wr2; fout = 128; ngc = 4; e = idx - 98304; }
    else if (idx < 147456) { src = Wl3; fout = 64;  ngc = 2; e = idx - 131072; }
    else                   { src = Wr3; fout = 64;  ngc = 2; e = idx - 147456; }

    int big = e >> 7;
    int r = e & 127;
    int lane = r >> 2, nt = r & 3;
    int gid = lane >> 2, tig = lane & 3;
    int ng = big % ngc;
    int t2 = big / ngc;
    int breg = t2 & 1;
    int part = (t2 >> 1) & 1;
    int kb = t2 >> 2;
    int row = kb * 8 + tig + breg * 4;
    int col = ng * 32 + nt * 8 + gid;
    float v = src[row * fout + col];
    unsigned hi = cvt_tf32(v);
    unsigned outv = hi;
    if (part) outv = cvt_tf32(v - __uint_as_float(hi));
    WPACKU[idx] = outv;
}

// ---------------------------------------------------------------------------
// XL = X @ Wl, XR = X @ Wr via m16n8k8 tf32 (3-term split) + fused dl/dr.
// MMA issue order is term-major: all (L,R)x(nt) for Ah*Bh, then Al*Bh, then
// Ah*Bl -> dependent accumulator reuse distance 8 instead of 1.
// ---------------------------------------------------------------------------
template <int FOUT>
__device__ void dual_matmul_mma(const unsigned* __restrict__ baseL,
                                const unsigned* __restrict__ baseR,
                                const float* xbuf, float* xlbuf, float* xrbuf,
                                const float* __restrict__ att,
                                float* DLp, float* DRp)
{
    constexpr int NG = FOUT / 32;          // 4 or 2
    constexpr int NWARPS = 4 * NG;         // 16 or 8
    const int w = threadIdx.x >> 5;
    if (w >= NWARPS) return;
    const int lane = threadIdx.x & 31;
    const int gid = lane >> 2, tig = lane & 3;
    const int mt = w / NG, ng = w % NG;
    const int m0 = mt * 16;
    const int n0 = ng * 32;

    float dL[4][4], dR[4][4];
#pragma unroll
    for (int nt = 0; nt < 4; nt++)
#pragma unroll
        for (int q = 0; q < 4; q++) { dL[nt][q] = 0.f; dR[nt][q] = 0.f; }

    constexpr int KB_STRIDE = 4 * NG * 128;
    constexpr int OFS = NG * 128;
    const unsigned* pL = baseL + ng * 128 + lane * 4;
    const unsigned* pR = baseR + ng * 128 + lane * 4;
    const float* xrow = xbuf + (m0 + gid) * RS + tig;

#pragma unroll 2
    for (int kb = 0; kb < 16; kb++) {
        float a0f = xrow[kb * 8];
        float a1f = xrow[kb * 8 + 8 * RS];
        float a2f = xrow[kb * 8 + 4];
        float a3f = xrow[kb * 8 + 8 * RS + 4];
        unsigned ah0 = cvt_tf32(a0f), ah1 = cvt_tf32(a1f);
        unsigned ah2 = cvt_tf32(a2f), ah3 = cvt_tf32(a3f);
        unsigned al0 = cvt_tf32(a0f - __uint_as_float(ah0));
        unsigned al1 = cvt_tf32(a1f - __uint_as_float(ah1));
        unsigned al2 = cvt_tf32(a2f - __uint_as_float(ah2));
        unsigned al3 = cvt_tf32(a3f - __uint_as_float(ah3));

        const unsigned* qL = pL + kb * KB_STRIDE;
        const unsigned* qR = pR + kb * KB_STRIDE;
        uint4 LhB0 = *(const uint4*)(qL);
        uint4 LhB1 = *(const uint4*)(qL + OFS);
        uint4 LlB0 = *(const uint4*)(qL + 2 * OFS);
        uint4 LlB1 = *(const uint4*)(qL + 3 * OFS);
        uint4 RhB0 = *(const uint4*)(qR);
        uint4 RhB1 = *(const uint4*)(qR + OFS);
        uint4 RlB0 = *(const uint4*)(qR + 2 * OFS);
        uint4 RlB1 = *(const uint4*)(qR + 3 * OFS);

        const unsigned* lh0 = (const unsigned*)&LhB0;
        const unsigned* lh1 = (const unsigned*)&LhB1;
        const unsigned* ll0 = (const unsigned*)&LlB0;
        const unsigned* ll1 = (const unsigned*)&LlB1;
        const unsigned* rh0 = (const unsigned*)&RhB0;
        const unsigned* rh1 = (const unsigned*)&RhB1;
        const unsigned* rl0 = (const unsigned*)&RlB0;
        const unsigned* rl1 = (const unsigned*)&RlB1;

        // term-major issue: Ah*Bh (L,R x nt), then Al*Bh, then Ah*Bl.
#pragma unroll
        for (int nt = 0; nt < 4; nt++) {
            mma_tf32(dL[nt], ah0, ah1, ah2, ah3, lh0[nt], lh1[nt]);
            mma_tf32(dR[nt], ah0, ah1, ah2, ah3, rh0[nt], rh1[nt]);
        }
#pragma unroll
        for (int nt = 0; nt < 4; nt++) {
            mma_tf32(dL[nt], al0, al1, al2, al3, lh0[nt], lh1[nt]);
            mma_tf32(dR[nt], al0, al1, al2, al3, rh0[nt], rh1[nt]);
        }
#pragma unroll
        for (int nt = 0; nt < 4; nt++) {
            mma_tf32(dL[nt], ah0, ah1, ah2, ah3, ll0[nt], ll1[nt]);
            mma_tf32(dR[nt], ah0, ah1, ah2, ah3, rl0[nt], rl1[nt]);
        }
    }

    const int rowa = m0 + gid, rowb = m0 + gid + 8;
#pragma unroll
    for (int nt = 0; nt < 4; nt++) {
        const int col = n0 + nt * 8 + 2 * tig;
        *(float2*)(xlbuf + rowa * RS + col) = make_float2(dL[nt][0], dL[nt][1]);
        *(float2*)(xlbuf + rowb * RS + col) = make_float2(dL[nt][2], dL[nt][3]);
        *(float2*)(xrbuf + rowa * RS + col) = make_float2(dR[nt][0], dR[nt][1]);
        *(float2*)(xrbuf + rowb * RS + col) = make_float2(dR[nt][2], dR[nt][3]);
    }

    // fused dl/dr partial over this warp's 32 columns.
    float pal = 0.f, pbl = 0.f, par = 0.f, pbr = 0.f;
#pragma unroll
    for (int nt = 0; nt < 4; nt++) {
        float2 av = *(const float2*)(att + n0 + nt * 8 + 2 * tig);
        pal = fmaf(dL[nt][0], av.x, fmaf(dL[nt][1], av.y, pal));
        pbl = fmaf(dL[nt][2], av.x, fmaf(dL[nt][3], av.y, pbl));
        par = fmaf(dR[nt][0], av.x, fmaf(dR[nt][1], av.y, par));
        pbr = fmaf(dR[nt][2], av.x, fmaf(dR[nt][3], av.y, pbr));
    }
#pragma unroll
    for (int o = 1; o < 4; o <<= 1) {
        pal += __shfl_xor_sync(0xffffffffu, pal, o);
        pbl += __shfl_xor_sync(0xffffffffu, pbl, o);
        par += __shfl_xor_sync(0xffffffffu, par, o);
        pbr += __shfl_xor_sync(0xffffffffu, pbr, o);
    }
    if (tig == 0) {
        DLp[rowa * NG + ng] = pal;
        DLp[rowb * NG + ng] = pbl;
        DRp[rowa * NG + ng] = par;
        DRp[rowb * NG + ng] = pbr;
    }
}

// ---------------------------------------------------------------------------
// compute_e + fused softmax (512 threads). Dual accumulators (chain 8 -> 4).
// DL3PART: HH==1 reads dl_i = DL[2i]+DL[2i+1].
// ---------------------------------------------------------------------------
template <int HH, int CC, bool DL3PART>
__device__ void compute_e_softmax(const float* xlbuf, const float* xrbuf,
                                  const float* __restrict__ att,
                                  const float* DLp, const float* DRp,
                                  float* ebuf, const int* imp, float* MS, float* SS)
{
    const int t = threadIdx.x;
    const int j = t & 63;
    const int rest = t >> 6;
    const int h = rest % HH;
    const int ic = rest / HH;
    constexpr int ICNT = 8 * HH;        // 32 (L1/2) or 8 (L3)
    const int i0 = ic * ICNT;
    constexpr uint64_t ABSM = 0x7FFFFFFF7FFFFFFFULL;

    float eacc[ICNT];
#pragma unroll
    for (int ii = 0; ii < ICNT; ii++) eacc[ii] = 0.f;

#pragma unroll
    for (int ch = 0; ch < CC / 16; ch++) {
        uint64_t xr2[8], av2[8];
        {
            const ulonglong2* xp = (const ulonglong2*)(xrbuf + j * RS + h * CC + ch * 16);
            const ulonglong2* ap = (const ulonglong2*)(att + h * CC + ch * 16);
#pragma unroll
            for (int q = 0; q < 4; q++) {
                ulonglong2 xv = xp[q]; xr2[2*q] = xv.x; xr2[2*q+1] = xv.y;
                ulonglong2 av = ap[q]; av2[2*q] = av.x; av2[2*q+1] = av.y;
            }
        }
#pragma unroll
        for (int ii = 0; ii < ICNT; ii++) {
            const ulonglong2* xl2 = (const ulonglong2*)(xlbuf + (i0 + ii) * RS + h * CC + ch * 16);
            uint64_t s2a = 0ull, s2b = 0ull;   // dual accumulators
#pragma unroll
            for (int q = 0; q < 4; q++) {
                ulonglong2 xv = xl2[q];
                uint64_t z0 = fadd2(xv.x, xr2[2*q])     & ABSM;
                uint64_t z1 = fadd2(xv.y, xr2[2*q + 1]) & ABSM;
                ffma2(s2a, z0, av2[2*q], s2a);
                ffma2(s2b, z1, av2[2*q + 1], s2b);
            }
            float2 sa = upk2(s2a);
            float2 sb = upk2(s2b);
            eacc[ii] += (sa.x + sa.y) + (sb.x + sb.y);
        }
    }

    const int impj = imp[j];
    float drv;
    if constexpr (DL3PART) drv = DRp[j * 2] + DRp[j * 2 + 1];
    else                   drv = DRp[j * HH + h];
#pragma unroll
    for (int ii = 0; ii < ICNT; ii++) {
        const int i = i0 + ii;
        float dlv;
        if constexpr (DL3PART) dlv = DLp[i * 2] + DLp[i * 2 + 1];
        else                   dlv = DLp[i * HH + h];
        float e = fmaf(0.4f, eacc[ii], 0.6f * (dlv + drv));
        bool ok = (i == j) || (impj && imp[i]);
        eacc[ii] = ok ? e : NEGV;
    }

    float m_t = eacc[0];
#pragma unroll
    for (int ii = 1; ii < ICNT; ii++) m_t = fmaxf(m_t, eacc[ii]);
    float s_t = 0.f;
#pragma unroll
    for (int ii = 0; ii < ICNT; ii++) {
        float ex = __expf(eacc[ii] - m_t);
        eacc[ii] = ex;
        s_t += ex;
    }
    MS[t] = m_t; SS[t] = s_t;
    __syncthreads();

    constexpr int NG2 = 8 / HH;
    const int base = t & (64 * HH - 1);
    float M = -3.4e38f;
#pragma unroll
    for (int g = 0; g < NG2; g++) M = fmaxf(M, MS[base + g * 64 * HH]);
    float S = 0.f;
#pragma unroll
    for (int g = 0; g < NG2; g++)
        S = fmaf(SS[base + g * 64 * HH], __expf(MS[base + g * 64 * HH] - M), S);
    const float kfac = __expf(m_t - M) / S;

    float* dst = ebuf + (h * 64 + j) * EJS + i0;
#pragma unroll
    for (int ii = 0; ii < ICNT; ii += 4) {
        float4 o;
        o.x = eacc[ii] * kfac;     o.y = eacc[ii + 1] * kfac;
        o.z = eacc[ii + 2] * kfac; o.w = eacc[ii + 3] * kfac;
        *(float4*)(dst + ii) = o;
    }
}

// ---------------------------------------------------------------------------
// out[j][f] = sum_i alpha[h][j][i] * xl[i][f] + bias[f]  (r10 layout)
// ---------------------------------------------------------------------------
template <int CC, int FOUT>
__device__ void aggregate(const float* xlbuf, const float* ebuf,
                          const float* __restrict__ bias, float* dst, int ds)
{
    const int t = threadIdx.x;
    const int j = t & 63;
    const int fs = t >> 6;
    constexpr int FW = FOUT / 8;        // 16 or 8
    const int f0 = fs * FW;
    const int h = f0 / CC;
    const float* arow = ebuf + (h * 64 + j) * EJS;

    uint64_t acc[FW / 2];
#pragma unroll
    for (int c = 0; c < FW / 2; c++) acc[c] = 0ull;

#pragma unroll 2
    for (int ib = 0; ib < 64; ib += 4) {
        float4 a4 = *(const float4*)(arow + ib);
#pragma unroll
        for (int u = 0; u < 4; u++) {
            float as = (u == 0) ? a4.x : (u == 1) ? a4.y : (u == 2) ? a4.z : a4.w;
            uint64_t ap = pk2(as, as);
            const float* xlr = xlbuf + (ib + u) * RS + f0;
#pragma unroll
            for (int c = 0; c < FW / 2; c += 2) {
                ulonglong2 xv = *(const ulonglong2*)(xlr + c * 2);
                ffma2(acc[c],     ap, xv.x, acc[c]);
                ffma2(acc[c + 1], ap, xv.y, acc[c + 1]);
            }
        }
    }
#pragma unroll
    for (int c = 0; c < FW / 2; c += 2) {
        float2 lo = upk2(acc[c]);
        float2 hi = upk2(acc[c + 1]);
        float4 bv = *(const float4*)(bias + f0 + c * 2);
        float4 o;
        o.x = lo.x + bv.x; o.y = lo.y + bv.y;
        o.z = hi.x + bv.z; o.w = hi.y + bv.w;
        *(float4*)(dst + j * ds + f0 + c * 2) = o;
    }
}

// layernorm over 128 features + relu, in place. Warp per row, 4 rows per warp.
__device__ void ln_relu(float* xbuf, const float* __restrict__ g, const float* __restrict__ bb)
{
    const int w = threadIdx.x >> 5;
    const int lane = threadIdx.x & 31;
    for (int r = w; r < 64; r += 16) {
        float4 v = *(const float4*)(xbuf + r * RS + lane * 4);
        float sum = v.x + v.y + v.z + v.w;
        float sq  = v.x*v.x + v.y*v.y + v.z*v.z + v.w*v.w;
#pragma unroll
        for (int o = 16; o > 0; o >>= 1) {
            sum += __shfl_xor_sync(0xffffffffu, sum, o);
            sq  += __shfl_xor_sync(0xffffffffu, sq, o);
        }
        float mean = sum * (1.f / 128.f);
        float var  = sq * (1.f / 128.f) - mean * mean;
        float rstd = rsqrtf(var + 1e-5f);
        float4 gg = *(const float4*)(g + lane * 4);
        float4 bv = *(const float4*)(bb + lane * 4);
        float4 o;
        o.x = fmaxf((v.x - mean) * rstd * gg.x + bv.x, 0.f);
        o.y = fmaxf((v.y - mean) * rstd * gg.y + bv.y, 0.f);
        o.z = fmaxf((v.z - mean) * rstd * gg.z + bv.z, 0.f);
        o.w = fmaxf((v.w - mean) * rstd * gg.w + bv.w, 0.f);
        *(float4*)(xbuf + r * RS + lane * 4) = o;
    }
}

__global__ void __launch_bounds__(NT, 1)
GNN_61040075210810_kernel(
    const float* __restrict__ team_obs, const float* __restrict__ target_obs,
    const float* __restrict__ team_mask, const float* __restrict__ ltm,
    const float* __restrict__ W_emb, const float* __restrict__ b_emb,
    const float* __restrict__ att1, const float* __restrict__ b1,
    const float* __restrict__ att2, const float* __restrict__ b2,
    const float* __restrict__ att3, const float* __restrict__ b3,
    const float* __restrict__ ln1g, const float* __restrict__ ln1b,
    const float* __restrict__ ln2g, const float* __restrict__ ln2b,
    float* __restrict__ out)
{
    extern __shared__ float smf[];
    float* X  = smf + OFF_X;
    float* XL = smf + OFF_XL;
    float* XR = smf + OFF_XR;
    float* E  = smf + OFF_E;
    float* MS = smf + OFF_MS;
    float* SS = smf + OFF_SS;
    int*   IMP = (int*)(smf + OFF_IMP);
    float* DL = smf + OFF_DL;
    float* DR = smf + OFF_DR;

    const int b = blockIdx.x;
    const int t = threadIdx.x;

    // ---- feature assembly ----
    float* FIN = E;
    for (int idx = t; idx < 1024; idx += NT) {
        int m = idx >> 4, k = idx & 15;
        float v;
        if (m < 16) {
            v = (k < 14) ? team_obs[(b * 16 + m) * 14 + k] : 0.f;
        } else {
            int tt = m - 16;
            if (k < 12)      v = target_obs[(b * 48 + tt) * 15 + k];
            else if (k < 14) v = 0.f;
            else             v = target_obs[(b * 48 + tt) * 15 + (k - 2)];
        }
        FIN[idx] = v;
    }
    if (t < 64) {
        bool ok = (t < 16) ? (team_mask[b * 32 + t] != NEGV)
                           : (ltm[b * 49 + (t - 16)] != 0.0f);
        IMP[t] = ok ? 1 : 0;
    }
    __syncthreads();

    // ---- embedding ----
    {
        const int w = t >> 5, lane = t & 31;
        const int row0 = w * 4;
        float acc[4][4];
#pragma unroll
        for (int r = 0; r < 4; r++)
#pragma unroll
            for (int c = 0; c < 4; c++) acc[r][c] = 0.f;
#pragma unroll
        for (int k = 0; k < 16; k++) {
            float xv[4];
#pragma unroll
            for (int r = 0; r < 4; r++) xv[r] = FIN[(row0 + r) * 16 + k];
            float4 wv = *(const float4*)(W_emb + k * 128 + lane * 4);
#pragma unroll
            for (int r = 0; r < 4; r++) {
                acc[r][0] = fmaf(xv[r], wv.x, acc[r][0]);
                acc[r][1] = fmaf(xv[r], wv.y, acc[r][1]);
                acc[r][2] = fmaf(xv[r], wv.z, acc[r][2]);
                acc[r][3] = fmaf(xv[r], wv.w, acc[r][3]);
            }
        }
        float4 be = *(const float4*)(b_emb + lane * 4);
#pragma unroll
        for (int r = 0; r < 4; r++) {
            float4 o;
            o.x = acc[r][0] + be.x; o.y = acc[r][1] + be.y;
            o.z = acc[r][2] + be.z; o.w = acc[r][3] + be.w;
            *(float4*)(X + (row0 + r) * RS + lane * 4) = o;
        }
    }
    __syncthreads();

    // ---- layer 1 ----
    dual_matmul_mma<128>(WPACKU + U_WL1, WPACKU + U_WR1, X, XL, XR, att1, DL, DR);
    __syncthreads();
    compute_e_softmax<4, 32, false>(XL, XR, att1, DL, DR, E, IMP, MS, SS);
    __syncthreads();
    aggregate<32, 128>(XL, E, b1, X, RS);
    __syncthreads();
    ln_relu(X, ln1g, ln1b);
    __syncthreads();

    // ---- layer 2 ----
    dual_matmul_mma<128>(WPACKU + U_WL2, WPACKU + U_WR2, X, XL, XR, att2, DL, DR);
    __syncthreads();
    compute_e_softmax<4, 32, false>(XL, XR, att2, DL, DR, E, IMP, MS, SS);
    __syncthreads();
    aggregate<32, 128>(XL, E, b2, X, RS);
    __syncthreads();
    ln_relu(X, ln2g, ln2b);
    __syncthreads();

    // ---- layer 3 (dl/dr fused into GEMM epilogue as 2 partials/row) ----
    dual_matmul_mma<64>(WPACKU + U_WL3, WPACKU + U_WR3, X, XL, XR, att3, DL, DR);
    __syncthreads();
    compute_e_softmax<1, 64, true>(XL, XR, att3, DL, DR, E, IMP, MS, SS);
    __syncthreads();
    aggregate<64, 64>(XL, E, b3, out + b * 64 * 64, 64);
}

extern "C" void kernel_launch(void* const* d_in, const int* in_sizes, int n_in,
                              void* d_out, int out_size)
{
    (void)in_sizes; (void)n_in; (void)out_size;
    pack_weights_tf32<<<640, 256>>>(
        (const float*)d_in[6],  (const float*)d_in[7],
        (const float*)d_in[10], (const float*)d_in[11],
        (const float*)d_in[14], (const float*)d_in[15]);

    cudaFuncSetAttribute(GNN_61040075210810_kernel,
                         cudaFuncAttributeMaxDynamicSharedMemorySize, SMEM_BYTES);
    GNN_61040075210810_kernel<<<128, NT, SMEM_BYTES>>>(
        (const float*)d_in[0],  (const float*)d_in[1],
        (const float*)d_in[2],  (const float*)d_in[3],
        (const float*)d_in[4],  (const float*)d_in[5],
        (const float*)d_in[8],  (const float*)d_in[9],
        (const float*)d_in[12], (const float*)d_in[13],
        (const float*)d_in[16], (const float*)d_in[17],
        (const float*)d_in[18], (const float*)d_in[19],
        (const float*)d_in[20], (const float*)d_in[21],
        (float*)d_out);
}

// round 15
// speedup vs baseline: 1.6131x; 1.0466x over previous
#include <cuda_runtime.h>
#include <cstdint>

// GATv2 GNN, one CTA per batch element, 512 threads.
// Round 15: r12 base + A-operand tf32 hi/lo split hoisted out of the GEMM:
// embedding/ln_relu epilogues write packed tf32 planes EH (in-place over X)
// and EL (new region); GEMM loads fragments with zero cvt/sub.

#define RS 132
#define NT 512
#define EJS 68
#define NEGV -1000000000.0f

#define OFF_X   0                        // fp32 aggregate out, then EH (u32) in place
#define OFF_XL  (64*RS)
#define OFF_XR  (2*64*RS)
#define OFF_E   (3*64*RS)
#define E_FLOATS (4*64*EJS)
#define OFF_MS  (OFF_E + E_FLOATS)
#define OFF_SS  (OFF_MS + 512)
#define OFF_IMP (OFF_SS + 512)
#define OFF_DL  (OFF_IMP + 64)
#define OFF_DR  (OFF_DL + 256)
#define OFF_EL  (OFF_DR + 256)           // tf32 lo plane (u32), stride RS
#define SMEM_FLOATS (OFF_EL + 64*RS)
#define SMEM_BYTES  (SMEM_FLOATS * 4)    // 211200 B

// Fragment-packed tf32 weights (layout documented in pack kernel).
__device__ __align__(16) unsigned WPACKU[163840];
#define U_WL1 0
#define U_WR1 32768
#define U_WL2 65536
#define U_WR2 98304
#define U_WL3 131072
#define U_WR3 147456

__device__ __forceinline__ unsigned cvt_tf32(float f) {
    unsigned u; asm("cvt.rna.tf32.f32 %0, %1;" : "=r"(u) : "f"(f)); return u;
}

// ---- packed f32x2 helpers ----
__device__ __forceinline__ uint64_t pk2(float lo, float hi) {
    uint64_t d; asm("mov.b64 %0, {%1, %2};" : "=l"(d) : "f"(lo), "f"(hi)); return d;
}
__device__ __forceinline__ float2 upk2(uint64_t v) {
    float lo, hi; asm("mov.b64 {%0, %1}, %2;" : "=f"(lo), "=f"(hi) : "l"(v));
    return make_float2(lo, hi);
}
__device__ __forceinline__ uint64_t fadd2(uint64_t a, uint64_t b) {
    uint64_t d; asm("add.rn.f32x2 %0, %1, %2;" : "=l"(d) : "l"(a), "l"(b)); return d;
}
__device__ __forceinline__ void ffma2(uint64_t& d, uint64_t a, uint64_t b, uint64_t c) {
    asm("fma.rn.f32x2 %0, %1, %2, %3;" : "=l"(d) : "l"(a), "l"(b), "l"(c));
}

__device__ __forceinline__ void mma_tf32(float* d, unsigned a0, unsigned a1,
                                         unsigned a2, unsigned a3,
                                         unsigned b0, unsigned b1) {
    asm volatile(
        "mma.sync.aligned.m16n8k8.row.col.f32.tf32.tf32.f32 "
        "{%0,%1,%2,%3}, {%4,%5,%6,%7}, {%8,%9}, {%0,%1,%2,%3};"
        : "+f"(d[0]), "+f"(d[1]), "+f"(d[2]), "+f"(d[3])
        : "r"(a0), "r"(a1), "r"(a2), "r"(a3), "r"(b0), "r"(b1));
}

// split a float into tf32 hi/lo
__device__ __forceinline__ void split_tf32(float v, unsigned& hi, unsigned& lo) {
    hi = cvt_tf32(v);
    lo = cvt_tf32(v - __uint_as_float(hi));
}

// ---------------------------------------------------------------------------
// Weight pack kernel (identical layout to round 8).
// ---------------------------------------------------------------------------
__global__ void pack_weights_tf32(
    const float* __restrict__ Wl1, const float* __restrict__ Wr1,
    const float* __restrict__ Wl2, const float* __restrict__ Wr2,
    const float* __restrict__ Wl3, const float* __restrict__ Wr3)
{
    int idx = blockIdx.x * blockDim.x + threadIdx.x;
    if (idx >= 163840) return;
    const float* src; int fout, ngc, e;
    if      (idx < 32768)  { src = Wl1; fout = 128; ngc = 4; e = idx; }
    else if (idx < 65536)  { src = Wr1; fout = 128; ngc = 4; e = idx - 32768; }
    else if (idx < 98304)  { src = Wl2; fout = 128; ngc = 4; e = idx - 65536; }
    else if (idx < 131072) { src = Wr2; fout = 128; ngc = 4; e = idx - 98304; }
    else if (idx < 147456) { src = Wl3; fout = 64;  ngc = 2; e = idx - 131072; }
    else                   { src = Wr3; fout = 64;  ngc = 2; e = idx - 147456; }

    int big = e >> 7;
    int r = e & 127;
    int lane = r >> 2, nt = r & 3;
    int gid = lane >> 2, tig = lane & 3;
    int ng = big % ngc;
    int t2 = big / ngc;
    int breg = t2 & 1;
    int part = (t2 >> 1) & 1;
    int kb = t2 >> 2;
    int row = kb * 8 + tig + breg * 4;
    int col = ng * 32 + nt * 8 + gid;
    float v = src[row * fout + col];
    unsigned hi = cvt_tf32(v);
    unsigned outv = hi;
    if (part) outv = cvt_tf32(v - __uint_as_float(hi));
    WPACKU[idx] = outv;
}

// ---------------------------------------------------------------------------
// XL = X @ Wl, XR = X @ Wr via m16n8k8 tf32 (3-term split) + fused dl/dr.
// A operands pre-split: EH/EL planes (u32, stride RS). Zero cvt in loop.
// FOUT=128: full dl/dr per (row, head=ng). FOUT=64: 2 partials/row.
// ---------------------------------------------------------------------------
template <int FOUT>
__device__ void dual_matmul_mma(const unsigned* __restrict__ baseL,
                                const unsigned* __restrict__ baseR,
                                const unsigned* EH, const unsigned* ELo,
                                float* xlbuf, float* xrbuf,
                                const float* __restrict__ att,
                                float* DLp, float* DRp)
{
    constexpr int NG = FOUT / 32;          // 4 or 2
    constexpr int NWARPS = 4 * NG;         // 16 or 8
    const int w = threadIdx.x >> 5;
    if (w >= NWARPS) return;
    const int lane = threadIdx.x & 31;
    const int gid = lane >> 2, tig = lane & 3;
    const int mt = w / NG, ng = w % NG;
    const int m0 = mt * 16;
    const int n0 = ng * 32;

    float dL[4][4], dR[4][4];
#pragma unroll
    for (int nt = 0; nt < 4; nt++)
#pragma unroll
        for (int q = 0; q < 4; q++) { dL[nt][q] = 0.f; dR[nt][q] = 0.f; }

    constexpr int KB_STRIDE = 4 * NG * 128;
    constexpr int OFS = NG * 128;
    const unsigned* pL = baseL + ng * 128 + lane * 4;
    const unsigned* pR = baseR + ng * 128 + lane * 4;
    const unsigned* ehrow = EH + (m0 + gid) * RS + tig;
    const unsigned* elrow = ELo + (m0 + gid) * RS + tig;

#pragma unroll 2
    for (int kb = 0; kb < 16; kb++) {
        unsigned ah0 = ehrow[kb * 8];
        unsigned ah1 = ehrow[kb * 8 + 8 * RS];
        unsigned ah2 = ehrow[kb * 8 + 4];
        unsigned ah3 = ehrow[kb * 8 + 8 * RS + 4];
        unsigned al0 = elrow[kb * 8];
        unsigned al1 = elrow[kb * 8 + 8 * RS];
        unsigned al2 = elrow[kb * 8 + 4];
        unsigned al3 = elrow[kb * 8 + 8 * RS + 4];

        const unsigned* qL = pL + kb * KB_STRIDE;
        const unsigned* qR = pR + kb * KB_STRIDE;
        uint4 LhB0 = *(const uint4*)(qL);
        uint4 LhB1 = *(const uint4*)(qL + OFS);
        uint4 LlB0 = *(const uint4*)(qL + 2 * OFS);
        uint4 LlB1 = *(const uint4*)(qL + 3 * OFS);
        uint4 RhB0 = *(const uint4*)(qR);
        uint4 RhB1 = *(const uint4*)(qR + OFS);
        uint4 RlB0 = *(const uint4*)(qR + 2 * OFS);
        uint4 RlB1 = *(const uint4*)(qR + 3 * OFS);

        const unsigned* lh0 = (const unsigned*)&LhB0;
        const unsigned* lh1 = (const unsigned*)&LhB1;
        const unsigned* ll0 = (const unsigned*)&LlB0;
        const unsigned* ll1 = (const unsigned*)&LlB1;
        const unsigned* rh0 = (const unsigned*)&RhB0;
        const unsigned* rh1 = (const unsigned*)&RhB1;
        const unsigned* rl0 = (const unsigned*)&RlB0;
        const unsigned* rl1 = (const unsigned*)&RlB1;

#pragma unroll
        for (int nt = 0; nt < 4; nt++) {
            mma_tf32(dL[nt], ah0, ah1, ah2, ah3, lh0[nt], lh1[nt]);
            mma_tf32(dL[nt], al0, al1, al2, al3, lh0[nt], lh1[nt]);
            mma_tf32(dL[nt], ah0, ah1, ah2, ah3, ll0[nt], ll1[nt]);
            mma_tf32(dR[nt], ah0, ah1, ah2, ah3, rh0[nt], rh1[nt]);
            mma_tf32(dR[nt], al0, al1, al2, al3, rh0[nt], rh1[nt]);
            mma_tf32(dR[nt], ah0, ah1, ah2, ah3, rl0[nt], rl1[nt]);
        }
    }

    const int rowa = m0 + gid, rowb = m0 + gid + 8;
#pragma unroll
    for (int nt = 0; nt < 4; nt++) {
        const int col = n0 + nt * 8 + 2 * tig;
        *(float2*)(xlbuf + rowa * RS + col) = make_float2(dL[nt][0], dL[nt][1]);
        *(float2*)(xlbuf + rowb * RS + col) = make_float2(dL[nt][2], dL[nt][3]);
        *(float2*)(xrbuf + rowa * RS + col) = make_float2(dR[nt][0], dR[nt][1]);
        *(float2*)(xrbuf + rowb * RS + col) = make_float2(dR[nt][2], dR[nt][3]);
    }

    // fused dl/dr partial over this warp's 32 columns.
    float pal = 0.f, pbl = 0.f, par = 0.f, pbr = 0.f;
#pragma unroll
    for (int nt = 0; nt < 4; nt++) {
        float2 av = *(const float2*)(att + n0 + nt * 8 + 2 * tig);
        pal = fmaf(dL[nt][0], av.x, fmaf(dL[nt][1], av.y, pal));
        pbl = fmaf(dL[nt][2], av.x, fmaf(dL[nt][3], av.y, pbl));
        par = fmaf(dR[nt][0], av.x, fmaf(dR[nt][1], av.y, par));
        pbr = fmaf(dR[nt][2], av.x, fmaf(dR[nt][3], av.y, pbr));
    }
#pragma unroll
    for (int o = 1; o < 4; o <<= 1) {
        pal += __shfl_xor_sync(0xffffffffu, pal, o);
        pbl += __shfl_xor_sync(0xffffffffu, pbl, o);
        par += __shfl_xor_sync(0xffffffffu, par, o);
        pbr += __shfl_xor_sync(0xffffffffu, pbr, o);
    }
    if (tig == 0) {
        DLp[rowa * NG + ng] = pal;
        DLp[rowb * NG + ng] = pbl;
        DRp[rowa * NG + ng] = par;
        DRp[rowb * NG + ng] = pbr;
    }
}

// ---------------------------------------------------------------------------
// compute_e + fused softmax (512 threads). Writes alpha into E[h][j][i].
// DL3PART: HH==1 reads dl_i = DL[2i]+DL[2i+1].
// ---------------------------------------------------------------------------
template <int HH, int CC, bool DL3PART>
__device__ void compute_e_softmax(const float* xlbuf, const float* xrbuf,
                                  const float* __restrict__ att,
                                  const float* DLp, const float* DRp,
                                  float* ebuf, const int* imp, float* MS, float* SS)
{
    const int t = threadIdx.x;
    const int j = t & 63;
    const int rest = t >> 6;
    const int h = rest % HH;
    const int ic = rest / HH;
    constexpr int ICNT = 8 * HH;        // 32 (L1/2) or 8 (L3)
    const int i0 = ic * ICNT;
    constexpr uint64_t ABSM = 0x7FFFFFFF7FFFFFFFULL;

    float eacc[ICNT];
#pragma unroll
    for (int ii = 0; ii < ICNT; ii++) eacc[ii] = 0.f;

#pragma unroll
    for (int ch = 0; ch < CC / 16; ch++) {
        uint64_t xr2[8], av2[8];
        {
            const ulonglong2* xp = (const ulonglong2*)(xrbuf + j * RS + h * CC + ch * 16);
            const ulonglong2* ap = (const ulonglong2*)(att + h * CC + ch * 16);
#pragma unroll
            for (int q = 0; q < 4; q++) {
                ulonglong2 xv = xp[q]; xr2[2*q] = xv.x; xr2[2*q+1] = xv.y;
                ulonglong2 av = ap[q]; av2[2*q] = av.x; av2[2*q+1] = av.y;
            }
        }
#pragma unroll
        for (int ii = 0; ii < ICNT; ii++) {
            const ulonglong2* xl2 = (const ulonglong2*)(xlbuf + (i0 + ii) * RS + h * CC + ch * 16);
            uint64_t s2 = 0ull;
#pragma unroll
            for (int q = 0; q < 4; q++) {
                ulonglong2 xv = xl2[q];
                uint64_t z0 = fadd2(xv.x, xr2[2*q])     & ABSM;
                uint64_t z1 = fadd2(xv.y, xr2[2*q + 1]) & ABSM;
                ffma2(s2, z0, av2[2*q], s2);
                ffma2(s2, z1, av2[2*q + 1], s2);
            }
            float2 s = upk2(s2);
            eacc[ii] += s.x + s.y;
        }
    }

    const int impj = imp[j];
    float drv;
    if constexpr (DL3PART) drv = DRp[j * 2] + DRp[j * 2 + 1];
    else                   drv = DRp[j * HH + h];
#pragma unroll
    for (int ii = 0; ii < ICNT; ii++) {
        const int i = i0 + ii;
        float dlv;
        if constexpr (DL3PART) dlv = DLp[i * 2] + DLp[i * 2 + 1];
        else                   dlv = DLp[i * HH + h];
        float e = fmaf(0.4f, eacc[ii], 0.6f * (dlv + drv));
        bool ok = (i == j) || (impj && imp[i]);
        eacc[ii] = ok ? e : NEGV;
    }

    float m_t = eacc[0];
#pragma unroll
    for (int ii = 1; ii < ICNT; ii++) m_t = fmaxf(m_t, eacc[ii]);
    float s_t = 0.f;
#pragma unroll
    for (int ii = 0; ii < ICNT; ii++) {
        float ex = __expf(eacc[ii] - m_t);
        eacc[ii] = ex;
        s_t += ex;
    }
    MS[t] = m_t; SS[t] = s_t;
    __syncthreads();

    constexpr int NG2 = 8 / HH;
    const int base = t & (64 * HH - 1);
    float M = -3.4e38f;
#pragma unroll
    for (int g = 0; g < NG2; g++) M = fmaxf(M, MS[base + g * 64 * HH]);
    float S = 0.f;
#pragma unroll
    for (int g = 0; g < NG2; g++)
        S = fmaf(SS[base + g * 64 * HH], __expf(MS[base + g * 64 * HH] - M), S);
    const float kfac = __expf(m_t - M) / S;

    float* dst = ebuf + (h * 64 + j) * EJS + i0;
#pragma unroll
    for (int ii = 0; ii < ICNT; ii += 4) {
        float4 o;
        o.x = eacc[ii] * kfac;     o.y = eacc[ii + 1] * kfac;
        o.z = eacc[ii + 2] * kfac; o.w = eacc[ii + 3] * kfac;
        *(float4*)(dst + ii) = o;
    }
}

// ---------------------------------------------------------------------------
// out[j][f] = sum_i alpha[h][j][i] * xl[i][f] + bias[f]  (r10 layout)
// ---------------------------------------------------------------------------
template <int CC, int FOUT>
__device__ void aggregate(const float* xlbuf, const float* ebuf,
                          const float* __restrict__ bias, float* dst, int ds)
{
    const int t = threadIdx.x;
    const int j = t & 63;
    const int fs = t >> 6;
    constexpr int FW = FOUT / 8;        // 16 or 8
    const int f0 = fs * FW;
    const int h = f0 / CC;
    const float* arow = ebuf + (h * 64 + j) * EJS;

    uint64_t acc[FW / 2];
#pragma unroll
    for (int c = 0; c < FW / 2; c++) acc[c] = 0ull;

#pragma unroll 2
    for (int ib = 0; ib < 64; ib += 4) {
        float4 a4 = *(const float4*)(arow + ib);
#pragma unroll
        for (int u = 0; u < 4; u++) {
            float as = (u == 0) ? a4.x : (u == 1) ? a4.y : (u == 2) ? a4.z : a4.w;
            uint64_t ap = pk2(as, as);
            const float* xlr = xlbuf + (ib + u) * RS + f0;
#pragma unroll
            for (int c = 0; c < FW / 2; c += 2) {
                ulonglong2 xv = *(const ulonglong2*)(xlr + c * 2);
                ffma2(acc[c],     ap, xv.x, acc[c]);
                ffma2(acc[c + 1], ap, xv.y, acc[c + 1]);
            }
        }
    }
#pragma unroll
    for (int c = 0; c < FW / 2; c += 2) {
        float2 lo = upk2(acc[c]);
        float2 hi = upk2(acc[c + 1]);
        float4 bv = *(const float4*)(bias + f0 + c * 2);
        float4 o;
        o.x = lo.x + bv.x; o.y = lo.y + bv.y;
        o.z = hi.x + bv.z; o.w = hi.y + bv.w;
        *(float4*)(dst + j * ds + f0 + c * 2) = o;
    }
}

// layernorm + relu, reading fp32 X; writes tf32 hi in place (over X region)
// and tf32 lo to ELo. Warp per row, 4 rows per warp.
__device__ void ln_relu_split(float* xbuf, unsigned* elbuf,
                              const float* __restrict__ g, const float* __restrict__ bb)
{
    const int w = threadIdx.x >> 5;
    const int lane = threadIdx.x & 31;
    unsigned* ehbuf = (unsigned*)xbuf;
    for (int r = w; r < 64; r += 16) {
        float4 v = *(const float4*)(xbuf + r * RS + lane * 4);
        float sum = v.x + v.y + v.z + v.w;
        float sq  = v.x*v.x + v.y*v.y + v.z*v.z + v.w*v.w;
#pragma unroll
        for (int o = 16; o > 0; o >>= 1) {
            sum += __shfl_xor_sync(0xffffffffu, sum, o);
            sq  += __shfl_xor_sync(0xffffffffu, sq, o);
        }
        float mean = sum * (1.f / 128.f);
        float var  = sq * (1.f / 128.f) - mean * mean;
        float rstd = rsqrtf(var + 1e-5f);
        float4 gg = *(const float4*)(g + lane * 4);
        float4 bv = *(const float4*)(bb + lane * 4);
        float o0 = fmaxf((v.x - mean) * rstd * gg.x + bv.x, 0.f);
        float o1 = fmaxf((v.y - mean) * rstd * gg.y + bv.y, 0.f);
        float o2 = fmaxf((v.z - mean) * rstd * gg.z + bv.z, 0.f);
        float o3 = fmaxf((v.w - mean) * rstd * gg.w + bv.w, 0.f);
        uint4 hv, lv;
        split_tf32(o0, hv.x, lv.x);
        split_tf32(o1, hv.y, lv.y);
        split_tf32(o2, hv.z, lv.z);
        split_tf32(o3, hv.w, lv.w);
        *(uint4*)(ehbuf + r * RS + lane * 4) = hv;
        *(uint4*)(elbuf + r * RS + lane * 4) = lv;
    }
}

__global__ void __launch_bounds__(NT, 1)
GNN_61040075210810_kernel(
    const float* __restrict__ team_obs, const float* __restrict__ target_obs,
    const float* __restrict__ team_mask, const float* __restrict__ ltm,
    const float* __restrict__ W_emb, const float* __restrict__ b_emb,
    const float* __restrict__ att1, const float* __restrict__ b1,
    const float* __restrict__ att2, const float* __restrict__ b2,
    const float* __restrict__ att3, const float* __restrict__ b3,
    const float* __restrict__ ln1g, const float* __restrict__ ln1b,
    const float* __restrict__ ln2g, const float* __restrict__ ln2b,
    float* __restrict__ out)
{
    extern __shared__ float smf[];
    float* X  = smf + OFF_X;             // fp32 aggregate out / EH u32 plane
    unsigned* EH = (unsigned*)(smf + OFF_X);
    unsigned* ELo = (unsigned*)(smf + OFF_EL);
    float* XL = smf + OFF_XL;
    float* XR = smf + OFF_XR;
    float* E  = smf + OFF_E;
    float* MS = smf + OFF_MS;
    float* SS = smf + OFF_SS;
    int*   IMP = (int*)(smf + OFF_IMP);
    float* DL = smf + OFF_DL;
    float* DR = smf + OFF_DR;

    const int b = blockIdx.x;
    const int t = threadIdx.x;

    // ---- feature assembly ----
    float* FIN = E;
    for (int idx = t; idx < 1024; idx += NT) {
        int m = idx >> 4, k = idx & 15;
        float v;
        if (m < 16) {
            v = (k < 14) ? team_obs[(b * 16 + m) * 14 + k] : 0.f;
        } else {
            int tt = m - 16;
            if (k < 12)      v = target_obs[(b * 48 + tt) * 15 + k];
            else if (k < 14) v = 0.f;
            else             v = target_obs[(b * 48 + tt) * 15 + (k - 2)];
        }
        FIN[idx] = v;
    }
    if (t < 64) {
        bool ok = (t < 16) ? (team_mask[b * 32 + t] != NEGV)
                           : (ltm[b * 49 + (t - 16)] != 0.0f);
        IMP[t] = ok ? 1 : 0;
    }
    __syncthreads();

    // ---- embedding: write tf32 hi/lo planes directly ----
    {
        const int w = t >> 5, lane = t & 31;
        const int row0 = w * 4;
        float acc[4][4];
#pragma unroll
        for (int r = 0; r < 4; r++)
#pragma unroll
            for (int c = 0; c < 4; c++) acc[r][c] = 0.f;
#pragma unroll
        for (int k = 0; k < 16; k++) {
            float xv[4];
#pragma unroll
            for (int r = 0; r < 4; r++) xv[r] = FIN[(row0 + r) * 16 + k];
            float4 wv = *(const float4*)(W_emb + k * 128 + lane * 4);
#pragma unroll
            for (int r = 0; r < 4; r++) {
                acc[r][0] = fmaf(xv[r], wv.x, acc[r][0]);
                acc[r][1] = fmaf(xv[r], wv.y, acc[r][1]);
                acc[r][2] = fmaf(xv[r], wv.z, acc[r][2]);
                acc[r][3] = fmaf(xv[r], wv.w, acc[r][3]);
            }
        }
        float4 be = *(const float4*)(b_emb + lane * 4);
#pragma unroll
        for (int r = 0; r < 4; r++) {
            uint4 hv, lv;
            split_tf32(acc[r][0] + be.x, hv.x, lv.x);
            split_tf32(acc[r][1] + be.y, hv.y, lv.y);
            split_tf32(acc[r][2] + be.z, hv.z, lv.z);
            split_tf32(acc[r][3] + be.w, hv.w, lv.w);
            *(uint4*)(EH + (row0 + r) * RS + lane * 4) = hv;
            *(uint4*)(ELo + (row0 + r) * RS + lane * 4) = lv;
        }
    }
    __syncthreads();

    // ---- layer 1 ----
    dual_matmul_mma<128>(WPACKU + U_WL1, WPACKU + U_WR1, EH, ELo, XL, XR, att1, DL, DR);
    __syncthreads();
    compute_e_softmax<4, 32, false>(XL, XR, att1, DL, DR, E, IMP, MS, SS);
    __syncthreads();
    aggregate<32, 128>(XL, E, b1, X, RS);
    __syncthreads();
    ln_relu_split(X, ELo, ln1g, ln1b);
    __syncthreads();

    // ---- layer 2 ----
    dual_matmul_mma<128>(WPACKU + U_WL2, WPACKU + U_WR2, EH, ELo, XL, XR, att2, DL, DR);
    __syncthreads();
    compute_e_softmax<4, 32, false>(XL, XR, att2, DL, DR, E, IMP, MS, SS);
    __syncthreads();
    aggregate<32, 128>(XL, E, b2, X, RS);
    __syncthreads();
    ln_relu_split(X, ELo, ln2g, ln2b);
    __syncthreads();

    // ---- layer 3 (dl/dr fused into GEMM epilogue as 2 partials/row) ----
    dual_matmul_mma<64>(WPACKU + U_WL3, WPACKU + U_WR3, EH, ELo, XL, XR, att3, DL, DR);
    __syncthreads();
    compute_e_softmax<1, 64, true>(XL, XR, att3, DL, DR, E, IMP, MS, SS);
    __syncthreads();
    aggregate<64, 64>(XL, E, b3, out + b * 64 * 64, 64);
}

extern "C" void kernel_launch(void* const* d_in, const int* in_sizes, int n_in,
                              void* d_out, int out_size)
{
    (void)in_sizes; (void)n_in; (void)out_size;
    pack_weights_tf32<<<640, 256>>>(
        (const float*)d_in[6],  (const float*)d_in[7],
        (const float*)d_in[10], (const float*)d_in[11],
        (const float*)d_in[14], (const float*)d_in[15]);

    cudaFuncSetAttribute(GNN_61040075210810_kernel,
                         cudaFuncAttributeMaxDynamicSharedMemorySize, SMEM_BYTES);
    GNN_61040075210810_kernel<<<128, NT, SMEM_BYTES>>>(
        (const float*)d_in[0],  (const float*)d_in[1],
        (const float*)d_in[2],  (const float*)d_in[3],
        (const float*)d_in[4],  (const float*)d_in[5],
        (const float*)d_in[8],  (const float*)d_in[9],
        (const float*)d_in[12], (const float*)d_in[13],
        (const float*)d_in[16], (const float*)d_in[17],
        (const float*)d_in[18], (const float*)d_in[19],
        (const float*)d_in[20], (const float*)d_in[21],
        (float*)d_out);
}

// round 16
// speedup vs baseline: 1.6526x; 1.0245x over previous
#include <cuda_runtime.h>
#include <cstdint>

// GATv2 GNN, one CTA per batch element, 512 threads.
// Round 16: r15 champion + (a) non-volatile MMA asm (scheduler freedom),
// (b) kb-loop unroll 4 (deeper LDG pipelining). Everything else identical.

#define RS 132
#define NT 512
#define EJS 68
#define NEGV -1000000000.0f

#define OFF_X   0                        // fp32 aggregate out, then EH (u32) in place
#define OFF_XL  (64*RS)
#define OFF_XR  (2*64*RS)
#define OFF_E   (3*64*RS)
#define E_FLOATS (4*64*EJS)
#define OFF_MS  (OFF_E + E_FLOATS)
#define OFF_SS  (OFF_MS + 512)
#define OFF_IMP (OFF_SS + 512)
#define OFF_DL  (OFF_IMP + 64)
#define OFF_DR  (OFF_DL + 256)
#define OFF_EL  (OFF_DR + 256)           // tf32 lo plane (u32), stride RS
#define SMEM_FLOATS (OFF_EL + 64*RS)
#define SMEM_BYTES  (SMEM_FLOATS * 4)    // 211200 B

// Fragment-packed tf32 weights (layout documented in pack kernel).
__device__ __align__(16) unsigned WPACKU[163840];
#define U_WL1 0
#define U_WR1 32768
#define U_WL2 65536
#define U_WR2 98304
#define U_WL3 131072
#define U_WR3 147456

__device__ __forceinline__ unsigned cvt_tf32(float f) {
    unsigned u; asm("cvt.rna.tf32.f32 %0, %1;" : "=r"(u) : "f"(f)); return u;
}

// ---- packed f32x2 helpers ----
__device__ __forceinline__ uint64_t pk2(float lo, float hi) {
    uint64_t d; asm("mov.b64 %0, {%1, %2};" : "=l"(d) : "f"(lo), "f"(hi)); return d;
}
__device__ __forceinline__ float2 upk2(uint64_t v) {
    float lo, hi; asm("mov.b64 {%0, %1}, %2;" : "=f"(lo), "=f"(hi) : "l"(v));
    return make_float2(lo, hi);
}
__device__ __forceinline__ uint64_t fadd2(uint64_t a, uint64_t b) {
    uint64_t d; asm("add.rn.f32x2 %0, %1, %2;" : "=l"(d) : "l"(a), "l"(b)); return d;
}
__device__ __forceinline__ void ffma2(uint64_t& d, uint64_t a, uint64_t b, uint64_t c) {
    asm("fma.rn.f32x2 %0, %1, %2, %3;" : "=l"(d) : "l"(a), "l"(b), "l"(c));
}

// non-volatile: pure computation, lets ptxas interleave with loads
__device__ __forceinline__ void mma_tf32(float* d, unsigned a0, unsigned a1,
                                         unsigned a2, unsigned a3,
                                         unsigned b0, unsigned b1) {
    asm("mma.sync.aligned.m16n8k8.row.col.f32.tf32.tf32.f32 "
        "{%0,%1,%2,%3}, {%4,%5,%6,%7}, {%8,%9}, {%0,%1,%2,%3};"
        : "+f"(d[0]), "+f"(d[1]), "+f"(d[2]), "+f"(d[3])
        : "r"(a0), "r"(a1), "r"(a2), "r"(a3), "r"(b0), "r"(b1));
}

// split a float into tf32 hi/lo
__device__ __forceinline__ void split_tf32(float v, unsigned& hi, unsigned& lo) {
    hi = cvt_tf32(v);
    lo = cvt_tf32(v - __uint_as_float(hi));
}

// ---------------------------------------------------------------------------
// Weight pack kernel (identical layout to round 8).
// ---------------------------------------------------------------------------
__global__ void pack_weights_tf32(
    const float* __restrict__ Wl1, const float* __restrict__ Wr1,
    const float* __restrict__ Wl2, const float* __restrict__ Wr2,
    const float* __restrict__ Wl3, const float* __restrict__ Wr3)
{
    int idx = blockIdx.x * blockDim.x + threadIdx.x;
    if (idx >= 163840) return;
    const float* src; int fout, ngc, e;
    if      (idx < 32768)  { src = Wl1; fout = 128; ngc = 4; e = idx; }
    else if (idx < 65536)  { src = Wr1; fout = 128; ngc = 4; e = idx - 32768; }
    else if (idx < 98304)  { src = Wl2; fout = 128; ngc = 4; e = idx - 65536; }
    else if (idx < 131072) { src = Wr2; fout = 128; ngc = 4; e = idx - 98304; }
    else if (idx < 147456) { src = Wl3; fout = 64;  ngc = 2; e = idx - 131072; }
    else                   { src = Wr3; fout = 64;  ngc = 2; e = idx - 147456; }

    int big = e >> 7;
    int r = e & 127;
    int lane = r >> 2, nt = r & 3;
    int gid = lane >> 2, tig = lane & 3;
    int ng = big % ngc;
    int t2 = big / ngc;
    int breg = t2 & 1;
    int part = (t2 >> 1) & 1;
    int kb = t2 >> 2;
    int row = kb * 8 + tig + breg * 4;
    int col = ng * 32 + nt * 8 + gid;
    float v = src[row * fout + col];
    unsigned hi = cvt_tf32(v);
    unsigned outv = hi;
    if (part) outv = cvt_tf32(v - __uint_as_float(hi));
    WPACKU[idx] = outv;
}

// ---------------------------------------------------------------------------
// XL = X @ Wl, XR = X @ Wr via m16n8k8 tf32 (3-term split) + fused dl/dr.
// A operands pre-split: EH/EL planes (u32, stride RS). Zero cvt in loop.
// ---------------------------------------------------------------------------
template <int FOUT>
__device__ void dual_matmul_mma(const unsigned* __restrict__ baseL,
                                const unsigned* __restrict__ baseR,
                                const unsigned* EH, const unsigned* ELo,
                                float* xlbuf, float* xrbuf,
                                const float* __restrict__ att,
                                float* DLp, float* DRp)
{
    constexpr int NG = FOUT / 32;          // 4 or 2
    constexpr int NWARPS = 4 * NG;         // 16 or 8
    const int w = threadIdx.x >> 5;
    if (w >= NWARPS) return;
    const int lane = threadIdx.x & 31;
    const int gid = lane >> 2, tig = lane & 3;
    const int mt = w / NG, ng = w % NG;
    const int m0 = mt * 16;
    const int n0 = ng * 32;

    float dL[4][4], dR[4][4];
#pragma unroll
    for (int nt = 0; nt < 4; nt++)
#pragma unroll
        for (int q = 0; q < 4; q++) { dL[nt][q] = 0.f; dR[nt][q] = 0.f; }

    constexpr int KB_STRIDE = 4 * NG * 128;
    constexpr int OFS = NG * 128;
    const unsigned* pL = baseL + ng * 128 + lane * 4;
    const unsigned* pR = baseR + ng * 128 + lane * 4;
    const unsigned* ehrow = EH + (m0 + gid) * RS + tig;
    const unsigned* elrow = ELo + (m0 + gid) * RS + tig;

#pragma unroll 4
    for (int kb = 0; kb < 16; kb++) {
        unsigned ah0 = ehrow[kb * 8];
        unsigned ah1 = ehrow[kb * 8 + 8 * RS];
        unsigned ah2 = ehrow[kb * 8 + 4];
        unsigned ah3 = ehrow[kb * 8 + 8 * RS + 4];
        unsigned al0 = elrow[kb * 8];
        unsigned al1 = elrow[kb * 8 + 8 * RS];
        unsigned al2 = elrow[kb * 8 + 4];
        unsigned al3 = elrow[kb * 8 + 8 * RS + 4];

        const unsigned* qL = pL + kb * KB_STRIDE;
        const unsigned* qR = pR + kb * KB_STRIDE;
        uint4 LhB0 = *(const uint4*)(qL);
        uint4 LhB1 = *(const uint4*)(qL + OFS);
        uint4 LlB0 = *(const uint4*)(qL + 2 * OFS);
        uint4 LlB1 = *(const uint4*)(qL + 3 * OFS);
        uint4 RhB0 = *(const uint4*)(qR);
        uint4 RhB1 = *(const uint4*)(qR + OFS);
        uint4 RlB0 = *(const uint4*)(qR + 2 * OFS);
        uint4 RlB1 = *(const uint4*)(qR + 3 * OFS);

        const unsigned* lh0 = (const unsigned*)&LhB0;
        const unsigned* lh1 = (const unsigned*)&LhB1;
        const unsigned* ll0 = (const unsigned*)&LlB0;
        const unsigned* ll1 = (const unsigned*)&LlB1;
        const unsigned* rh0 = (const unsigned*)&RhB0;
        const unsigned* rh1 = (const unsigned*)&RhB1;
        const unsigned* rl0 = (const unsigned*)&RlB0;
        const unsigned* rl1 = (const unsigned*)&RlB1;

#pragma unroll
        for (int nt = 0; nt < 4; nt++) {
            mma_tf32(dL[nt], ah0, ah1, ah2, ah3, lh0[nt], lh1[nt]);
            mma_tf32(dL[nt], al0, al1, al2, al3, lh0[nt], lh1[nt]);
            mma_tf32(dL[nt], ah0, ah1, ah2, ah3, ll0[nt], ll1[nt]);
            mma_tf32(dR[nt], ah0, ah1, ah2, ah3, rh0[nt], rh1[nt]);
            mma_tf32(dR[nt], al0, al1, al2, al3, rh0[nt], rh1[nt]);
            mma_tf32(dR[nt], ah0, ah1, ah2, ah3, rl0[nt], rl1[nt]);
        }
    }

    const int rowa = m0 + gid, rowb = m0 + gid + 8;
#pragma unroll
    for (int nt = 0; nt < 4; nt++) {
        const int col = n0 + nt * 8 + 2 * tig;
        *(float2*)(xlbuf + rowa * RS + col) = make_float2(dL[nt][0], dL[nt][1]);
        *(float2*)(xlbuf + rowb * RS + col) = make_float2(dL[nt][2], dL[nt][3]);
        *(float2*)(xrbuf + rowa * RS + col) = make_float2(dR[nt][0], dR[nt][1]);
        *(float2*)(xrbuf + rowb * RS + col) = make_float2(dR[nt][2], dR[nt][3]);
    }

    // fused dl/dr partial over this warp's 32 columns.
    float pal = 0.f, pbl = 0.f, par = 0.f, pbr = 0.f;
#pragma unroll
    for (int nt = 0; nt < 4; nt++) {
        float2 av = *(const float2*)(att + n0 + nt * 8 + 2 * tig);
        pal = fmaf(dL[nt][0], av.x, fmaf(dL[nt][1], av.y, pal));
        pbl = fmaf(dL[nt][2], av.x, fmaf(dL[nt][3], av.y, pbl));
        par = fmaf(dR[nt][0], av.x, fmaf(dR[nt][1], av.y, par));
        pbr = fmaf(dR[nt][2], av.x, fmaf(dR[nt][3], av.y, pbr));
    }
#pragma unroll
    for (int o = 1; o < 4; o <<= 1) {
        pal += __shfl_xor_sync(0xffffffffu, pal, o);
        pbl += __shfl_xor_sync(0xffffffffu, pbl, o);
        par += __shfl_xor_sync(0xffffffffu, par, o);
        pbr += __shfl_xor_sync(0xffffffffu, pbr, o);
    }
    if (tig == 0) {
        DLp[rowa * NG + ng] = pal;
        DLp[rowb * NG + ng] = pbl;
        DRp[rowa * NG + ng] = par;
        DRp[rowb * NG + ng] = pbr;
    }
}

// ---------------------------------------------------------------------------
// compute_e + fused softmax (512 threads). Writes alpha into E[h][j][i].
// DL3PART: HH==1 reads dl_i = DL[2i]+DL[2i+1].
// ---------------------------------------------------------------------------
template <int HH, int CC, bool DL3PART>
__device__ void compute_e_softmax(const float* xlbuf, const float* xrbuf,
                                  const float* __restrict__ att,
                                  const float* DLp, const float* DRp,
                                  float* ebuf, const int* imp, float* MS, float* SS)
{
    const int t = threadIdx.x;
    const int j = t & 63;
    const int rest = t >> 6;
    const int h = rest % HH;
    const int ic = rest / HH;
    constexpr int ICNT = 8 * HH;        // 32 (L1/2) or 8 (L3)
    const int i0 = ic * ICNT;
    constexpr uint64_t ABSM = 0x7FFFFFFF7FFFFFFFULL;

    float eacc[ICNT];
#pragma unroll
    for (int ii = 0; ii < ICNT; ii++) eacc[ii] = 0.f;

#pragma unroll
    for (int ch = 0; ch < CC / 16; ch++) {
        uint64_t xr2[8], av2[8];
        {
            const ulonglong2* xp = (const ulonglong2*)(xrbuf + j * RS + h * CC + ch * 16);
            const ulonglong2* ap = (const ulonglong2*)(att + h * CC + ch * 16);
#pragma unroll
            for (int q = 0; q < 4; q++) {
                ulonglong2 xv = xp[q]; xr2[2*q] = xv.x; xr2[2*q+1] = xv.y;
                ulonglong2 av = ap[q]; av2[2*q] = av.x; av2[2*q+1] = av.y;
            }
        }
#pragma unroll
        for (int ii = 0; ii < ICNT; ii++) {
            const ulonglong2* xl2 = (const ulonglong2*)(xlbuf + (i0 + ii) * RS + h * CC + ch * 16);
            uint64_t s2 = 0ull;
#pragma unroll
            for (int q = 0; q < 4; q++) {
                ulonglong2 xv = xl2[q];
                uint64_t z0 = fadd2(xv.x, xr2[2*q])     & ABSM;
                uint64_t z1 = fadd2(xv.y, xr2[2*q + 1]) & ABSM;
                ffma2(s2, z0, av2[2*q], s2);
                ffma2(s2, z1, av2[2*q + 1], s2);
            }
            float2 s = upk2(s2);
            eacc[ii] += s.x + s.y;
        }
    }

    const int impj = imp[j];
    float drv;
    if constexpr (DL3PART) drv = DRp[j * 2] + DRp[j * 2 + 1];
    else                   drv = DRp[j * HH + h];
#pragma unroll
    for (int ii = 0; ii < ICNT; ii++) {
        const int i = i0 + ii;
        float dlv;
        if constexpr (DL3PART) dlv = DLp[i * 2] + DLp[i * 2 + 1];
        else                   dlv = DLp[i * HH + h];
        float e = fmaf(0.4f, eacc[ii], 0.6f * (dlv + drv));
        bool ok = (i == j) || (impj && imp[i]);
        eacc[ii] = ok ? e : NEGV;
    }

    float m_t = eacc[0];
#pragma unroll
    for (int ii = 1; ii < ICNT; ii++) m_t = fmaxf(m_t, eacc[ii]);
    float s_t = 0.f;
#pragma unroll
    for (int ii = 0; ii < ICNT; ii++) {
        float ex = __expf(eacc[ii] - m_t);
        eacc[ii] = ex;
        s_t += ex;
    }
    MS[t] = m_t; SS[t] = s_t;
    __syncthreads();

    constexpr int NG2 = 8 / HH;
    const int base = t & (64 * HH - 1);
    float M = -3.4e38f;
#pragma unroll
    for (int g = 0; g < NG2; g++) M = fmaxf(M, MS[base + g * 64 * HH]);
    float S = 0.f;
#pragma unroll
    for (int g = 0; g < NG2; g++)
        S = fmaf(SS[base + g * 64 * HH], __expf(MS[base + g * 64 * HH] - M), S);
    const float kfac = __expf(m_t - M) / S;

    float* dst = ebuf + (h * 64 + j) * EJS + i0;
#pragma unroll
    for (int ii = 0; ii < ICNT; ii += 4) {
        float4 o;
        o.x = eacc[ii] * kfac;     o.y = eacc[ii + 1] * kfac;
        o.z = eacc[ii + 2] * kfac; o.w = eacc[ii + 3] * kfac;
        *(float4*)(dst + ii) = o;
    }
}

// ---------------------------------------------------------------------------
// out[j][f] = sum_i alpha[h][j][i] * xl[i][f] + bias[f]  (r10 layout)
// ---------------------------------------------------------------------------
template <int CC, int FOUT>
__device__ void aggregate(const float* xlbuf, const float* ebuf,
                          const float* __restrict__ bias, float* dst, int ds)
{
    const int t = threadIdx.x;
    const int j = t & 63;
    const int fs = t >> 6;
    constexpr int FW = FOUT / 8;        // 16 or 8
    const int f0 = fs * FW;
    const int h = f0 / CC;
    const float* arow = ebuf + (h * 64 + j) * EJS;

    uint64_t acc[FW / 2];
#pragma unroll
    for (int c = 0; c < FW / 2; c++) acc[c] = 0ull;

#pragma unroll 2
    for (int ib = 0; ib < 64; ib += 4) {
        float4 a4 = *(const float4*)(arow + ib);
#pragma unroll
        for (int u = 0; u < 4; u++) {
            float as = (u == 0) ? a4.x : (u == 1) ? a4.y : (u == 2) ? a4.z : a4.w;
            uint64_t ap = pk2(as, as);
            const float* xlr = xlbuf + (ib + u) * RS + f0;
#pragma unroll
            for (int c = 0; c < FW / 2; c += 2) {
                ulonglong2 xv = *(const ulonglong2*)(xlr + c * 2);
                ffma2(acc[c],     ap, xv.x, acc[c]);
                ffma2(acc[c + 1], ap, xv.y, acc[c + 1]);
            }
        }
    }
#pragma unroll
    for (int c = 0; c < FW / 2; c += 2) {
        float2 lo = upk2(acc[c]);
        float2 hi = upk2(acc[c + 1]);
        float4 bv = *(const float4*)(bias + f0 + c * 2);
        float4 o;
        o.x = lo.x + bv.x; o.y = lo.y + bv.y;
        o.z = hi.x + bv.z; o.w = hi.y + bv.w;
        *(float4*)(dst + j * ds + f0 + c * 2) = o;
    }
}

// layernorm + relu, reading fp32 X; writes tf32 hi in place (over X region)
// and tf32 lo to ELo. Warp per row, 4 rows per warp.
__device__ void ln_relu_split(float* xbuf, unsigned* elbuf,
                              const float* __restrict__ g, const float* __restrict__ bb)
{
    const int w = threadIdx.x >> 5;
    const int lane = threadIdx.x & 31;
    unsigned* ehbuf = (unsigned*)xbuf;
    for (int r = w; r < 64; r += 16) {
        float4 v = *(const float4*)(xbuf + r * RS + lane * 4);
        float sum = v.x + v.y + v.z + v.w;
        float sq  = v.x*v.x + v.y*v.y + v.z*v.z + v.w*v.w;
#pragma unroll
        for (int o = 16; o > 0; o >>= 1) {
            sum += __shfl_xor_sync(0xffffffffu, sum, o);
            sq  += __shfl_xor_sync(0xffffffffu, sq, o);
        }
        float mean = sum * (1.f / 128.f);
        float var  = sq * (1.f / 128.f) - mean * mean;
        float rstd = rsqrtf(var + 1e-5f);
        float4 gg = *(const float4*)(g + lane * 4);
        float4 bv = *(const float4*)(bb + lane * 4);
        float o0 = fmaxf((v.x - mean) * rstd * gg.x + bv.x, 0.f);
        float o1 = fmaxf((v.y - mean) * rstd * gg.y + bv.y, 0.f);
        float o2 = fmaxf((v.z - mean) * rstd * gg.z + bv.z, 0.f);
        float o3 = fmaxf((v.w - mean) * rstd * gg.w + bv.w, 0.f);
        uint4 hv, lv;
        split_tf32(o0, hv.x, lv.x);
        split_tf32(o1, hv.y, lv.y);
        split_tf32(o2, hv.z, lv.z);
        split_tf32(o3, hv.w, lv.w);
        *(uint4*)(ehbuf + r * RS + lane * 4) = hv;
        *(uint4*)(elbuf + r * RS + lane * 4) = lv;
    }
}

__global__ void __launch_bounds__(NT, 1)
GNN_61040075210810_kernel(
    const float* __restrict__ team_obs, const float* __restrict__ target_obs,
    const float* __restrict__ team_mask, const float* __restrict__ ltm,
    const float* __restrict__ W_emb, const float* __restrict__ b_emb,
    const float* __restrict__ att1, const float* __restrict__ b1,
    const float* __restrict__ att2, const float* __restrict__ b2,
    const float* __restrict__ att3, const float* __restrict__ b3,
    const float* __restrict__ ln1g, const float* __restrict__ ln1b,
    const float* __restrict__ ln2g, const float* __restrict__ ln2b,
    float* __restrict__ out)
{
    extern __shared__ float smf[];
    float* X  = smf + OFF_X;             // fp32 aggregate out / EH u32 plane
    unsigned* EH = (unsigned*)(smf + OFF_X);
    unsigned* ELo = (unsigned*)(smf + OFF_EL);
    float* XL = smf + OFF_XL;
    float* XR = smf + OFF_XR;
    float* E  = smf + OFF_E;
    float* MS = smf + OFF_MS;
    float* SS = smf + OFF_SS;
    int*   IMP = (int*)(smf + OFF_IMP);
    float* DL = smf + OFF_DL;
    float* DR = smf + OFF_DR;

    const int b = blockIdx.x;
    const int t = threadIdx.x;

    // ---- feature assembly ----
    float* FIN = E;
    for (int idx = t; idx < 1024; idx += NT) {
        int m = idx >> 4, k = idx & 15;
        float v;
        if (m < 16) {
            v = (k < 14) ? team_obs[(b * 16 + m) * 14 + k] : 0.f;
        } else {
            int tt = m - 16;
            if (k < 12)      v = target_obs[(b * 48 + tt) * 15 + k];
            else if (k < 14) v = 0.f;
            else             v = target_obs[(b * 48 + tt) * 15 + (k - 2)];
        }
        FIN[idx] = v;
    }
    if (t < 64) {
        bool ok = (t < 16) ? (team_mask[b * 32 + t] != NEGV)
                           : (ltm[b * 49 + (t - 16)] != 0.0f);
        IMP[t] = ok ? 1 : 0;
    }
    __syncthreads();

    // ---- embedding: write tf32 hi/lo planes directly ----
    {
        const int w = t >> 5, lane = t & 31;
        const int row0 = w * 4;
        float acc[4][4];
#pragma unroll
        for (int r = 0; r < 4; r++)
#pragma unroll
            for (int c = 0; c < 4; c++) acc[r][c] = 0.f;
#pragma unroll
        for (int k = 0; k < 16; k++) {
            float xv[4];
#pragma unroll
            for (int r = 0; r < 4; r++) xv[r] = FIN[(row0 + r) * 16 + k];
            float4 wv = *(const float4*)(W_emb + k * 128 + lane * 4);
#pragma unroll
            for (int r = 0; r < 4; r++) {
                acc[r][0] = fmaf(xv[r], wv.x, acc[r][0]);
                acc[r][1] = fmaf(xv[r], wv.y, acc[r][1]);
                acc[r][2] = fmaf(xv[r], wv.z, acc[r][2]);
                acc[r][3] = fmaf(xv[r], wv.w, acc[r][3]);
            }
        }
        float4 be = *(const float4*)(b_emb + lane * 4);
#pragma unroll
        for (int r = 0; r < 4; r++) {
            uint4 hv, lv;
            split_tf32(acc[r][0] + be.x, hv.x, lv.x);
            split_tf32(acc[r][1] + be.y, hv.y, lv.y);
            split_tf32(acc[r][2] + be.z, hv.z, lv.z);
            split_tf32(acc[r][3] + be.w, hv.w, lv.w);
            *(uint4*)(EH + (row0 + r) * RS + lane * 4) = hv;
            *(uint4*)(ELo + (row0 + r) * RS + lane * 4) = lv;
        }
    }
    __syncthreads();

    // ---- layer 1 ----
    dual_matmul_mma<128>(WPACKU + U_WL1, WPACKU + U_WR1, EH, ELo, XL, XR, att1, DL, DR);
    __syncthreads();
    compute_e_softmax<4, 32, false>(XL, XR, att1, DL, DR, E, IMP, MS, SS);
    __syncthreads();
    aggregate<32, 128>(XL, E, b1, X, RS);
    __syncthreads();
    ln_relu_split(X, ELo, ln1g, ln1b);
    __syncthreads();

    // ---- layer 2 ----
    dual_matmul_mma<128>(WPACKU + U_WL2, WPACKU + U_WR2, EH, ELo, XL, XR, att2, DL, DR);
    __syncthreads();
    compute_e_softmax<4, 32, false>(XL, XR, att2, DL, DR, E, IMP, MS, SS);
    __syncthreads();
    aggregate<32, 128>(XL, E, b2, X, RS);
    __syncthreads();
    ln_relu_split(X, ELo, ln2g, ln2b);
    __syncthreads();

    // ---- layer 3 (dl/dr fused into GEMM epilogue as 2 partials/row) ----
    dual_matmul_mma<64>(WPACKU + U_WL3, WPACKU + U_WR3, EH, ELo, XL, XR, att3, DL, DR);
    __syncthreads();
    compute_e_softmax<1, 64, true>(XL, XR, att3, DL, DR, E, IMP, MS, SS);
    __syncthreads();
    aggregate<64, 64>(XL, E, b3, out + b * 64 * 64, 64);
}

extern "C" void kernel_launch(void* const* d_in, const int* in_sizes, int n_in,
                              void* d_out, int out_size)
{
    (void)in_sizes; (void)n_in; (void)out_size;
    pack_weights_tf32<<<640, 256>>>(
        (const float*)d_in[6],  (const float*)d_in[7],
        (const float*)d_in[10], (const float*)d_in[11],
        (const float*)d_in[14], (const float*)d_in[15]);

    cudaFuncSetAttribute(GNN_61040075210810_kernel,
                         cudaFuncAttributeMaxDynamicSharedMemorySize, SMEM_BYTES);
    GNN_61040075210810_kernel<<<128, NT, SMEM_BYTES>>>(
        (const float*)d_in[0],  (const float*)d_in[1],
        (const float*)d_in[2],  (const float*)d_in[3],
        (const float*)d_in[4],  (const float*)d_in[5],
        (const float*)d_in[8],  (const float*)d_in[9],
        (const float*)d_in[12], (const float*)d_in[13],
        (const float*)d_in[16], (const float*)d_in[17],
        (const float*)d_in[18], (const float*)d_in[19],
        (const float*)d_in[20], (const float*)d_in[21],
        (float*)d_out);
}